// round 1
// baseline (speedup 1.0000x reference)
#include <cuda_runtime.h>
#include <math.h>

#define BB  8
#define TT  512
#define DM  512
#define NHH 8
#define DHH 64

// Scratch (static __device__ — no allocations allowed)
__device__ float g_Q[BB*NHH*TT*DHH];     // [B,NH,T,DH], pre-scaled by 1/8
__device__ float g_K[BB*NHH*TT*DHH];
__device__ float g_V[BB*NHH*TT*DHH];
__device__ float g_P[BB*NHH*TT*TT];      // position scores [B,NH,T,T]
__device__ float g_ctx[BB*TT*DM];        // attention context [B,T,D]

// ---------------------------------------------------------------------------
// QKV projection GEMM: O = x @ W^T + b, written into head-major layout.
// 128x128 block tile, BK=8, 256 threads, 8x8 micro-tile.
// ---------------------------------------------------------------------------
__global__ __launch_bounds__(256) void qkv_gemm(
    const float* __restrict__ x,
    const float* __restrict__ Wq, const float* __restrict__ bq,
    const float* __restrict__ Wk, const float* __restrict__ bk,
    const float* __restrict__ Wv, const float* __restrict__ bv)
{
    const int which = blockIdx.z;
    const float* W    = (which==0) ? Wq : ((which==1) ? Wk : Wv);
    const float* bias = (which==0) ? bq : ((which==1) ? bk : bv);
    float* out        = (which==0) ? g_Q : ((which==1) ? g_K : g_V);
    const float scale = (which==0) ? 0.125f : 1.0f;   // 1/sqrt(DH) folded into Q

    __shared__ float As[8][132];
    __shared__ float Bsm[8][132];

    const int tid = threadIdx.x;
    const int tx = tid & 15, ty = tid >> 4;
    const int m0 = blockIdx.x * 128;
    const int n0 = blockIdx.y * 128;
    const int lrow = tid >> 1;
    const int lcol = (tid & 1) * 4;

    float acc[8][8];
    #pragma unroll
    for (int i = 0; i < 8; i++)
        #pragma unroll
        for (int j = 0; j < 8; j++) acc[i][j] = 0.f;

    const float* Ap = &x[(m0 + lrow) * DM + lcol];
    const float* Bp = &W[(n0 + lrow) * DM + lcol];

    for (int k0 = 0; k0 < DM; k0 += 8) {
        float4 av  = *(const float4*)(Ap + k0);
        float4 bv4 = *(const float4*)(Bp + k0);
        __syncthreads();
        As[lcol+0][lrow]=av.x;  As[lcol+1][lrow]=av.y;  As[lcol+2][lrow]=av.z;  As[lcol+3][lrow]=av.w;
        Bsm[lcol+0][lrow]=bv4.x;Bsm[lcol+1][lrow]=bv4.y;Bsm[lcol+2][lrow]=bv4.z;Bsm[lcol+3][lrow]=bv4.w;
        __syncthreads();
        #pragma unroll
        for (int kk = 0; kk < 8; kk++) {
            float4 a0 = *(const float4*)&As[kk][ty*4];
            float4 a1 = *(const float4*)&As[kk][ty*4 + 64];
            float4 b0 = *(const float4*)&Bsm[kk][tx*4];
            float4 b1 = *(const float4*)&Bsm[kk][tx*4 + 64];
            float a[8] = {a0.x,a0.y,a0.z,a0.w,a1.x,a1.y,a1.z,a1.w};
            float b[8] = {b0.x,b0.y,b0.z,b0.w,b1.x,b1.y,b1.z,b1.w};
            #pragma unroll
            for (int i = 0; i < 8; i++)
                #pragma unroll
                for (int j = 0; j < 8; j++) acc[i][j] += a[i]*b[j];
        }
    }

    // Write out in [B,NH,T,DH] layout with bias + scale
    #pragma unroll
    for (int jg = 0; jg < 2; jg++) {
        const int nb = n0 + jg*64 + tx*4;
        const float4 bsv = *(const float4*)&bias[nb];
        const int h = nb >> 6;
        const int d = nb & 63;
        #pragma unroll
        for (int i = 0; i < 8; i++) {
            const int r = m0 + ((i < 4) ? (ty*4 + i) : (64 + ty*4 + i - 4));
            const int b_ = r >> 9, t = r & 511;
            float4 o;
            o.x = (acc[i][jg*4+0] + bsv.x) * scale;
            o.y = (acc[i][jg*4+1] + bsv.y) * scale;
            o.z = (acc[i][jg*4+2] + bsv.z) * scale;
            o.w = (acc[i][jg*4+3] + bsv.w) * scale;
            *(float4*)&out[((b_*NHH + h)*TT + t)*DHH + d] = o;
        }
    }
}

// ---------------------------------------------------------------------------
// Position kernel: P[b,h,t,s] = Q[b,h,t,:] . rel_emb[t,s,h*64:...]
// One CTA per (t,h); rel row read from DRAM exactly once, reused across all
// 8 batches held in registers. 128 threads; each 8-lane group owns one s-row.
// ---------------------------------------------------------------------------
__global__ __launch_bounds__(128) void pos_kernel(const float* __restrict__ rel)
{
    const int t = blockIdx.x;
    const int h = blockIdx.y;
    const int tid  = threadIdx.x;
    const int lane = tid & 31;
    const int warp = tid >> 5;
    const int grp  = lane >> 3;   // which s within the warp's quad
    const int dl   = lane & 7;    // d-slice lane (8 floats each)

    // q[b][0..7]: Q values for this thread's d-slice, all 8 batches (Q pre-scaled)
    float q[8][8];
    #pragma unroll
    for (int b_ = 0; b_ < 8; b_++) {
        const float* qp = &g_Q[((b_*NHH + h)*TT + t)*DHH + dl*8];
        float4 q0 = *(const float4*)qp;
        float4 q1 = *(const float4*)(qp + 4);
        q[b_][0]=q0.x; q[b_][1]=q0.y; q[b_][2]=q0.z; q[b_][3]=q0.w;
        q[b_][4]=q1.x; q[b_][5]=q1.y; q[b_][6]=q1.z; q[b_][7]=q1.w;
    }

    for (int s = warp*4 + grp; s < TT; s += 16) {
        const float* rp = &rel[(t*TT + s)*DM + h*DHH + dl*8];
        float4 r0 = *(const float4*)rp;
        float4 r1 = *(const float4*)(rp + 4);
        float rv[8] = {r0.x,r0.y,r0.z,r0.w,r1.x,r1.y,r1.z,r1.w};
        float sum[8];
        #pragma unroll
        for (int b_ = 0; b_ < 8; b_++) {
            float a = 0.f;
            #pragma unroll
            for (int d = 0; d < 8; d++) a += q[b_][d] * rv[d];
            sum[b_] = a;
        }
        // reduce across the 8-lane group
        #pragma unroll
        for (int b_ = 0; b_ < 8; b_++) {
            sum[b_] += __shfl_xor_sync(0xffffffffu, sum[b_], 4);
            sum[b_] += __shfl_xor_sync(0xffffffffu, sum[b_], 2);
            sum[b_] += __shfl_xor_sync(0xffffffffu, sum[b_], 1);
        }
        // lane dl writes batch dl (static select, no local-mem spill)
        float outv = sum[0];
        #pragma unroll
        for (int b_ = 1; b_ < 8; b_++) if (dl == b_) outv = sum[b_];
        g_P[((dl*NHH + h)*TT + t)*TT + s] = outv;
    }
}

// ---------------------------------------------------------------------------
// Flash-style attention: per (b, h, 64-row t-chunk). Content GEMM from smem
// (+ precomputed position from g_P), online softmax, PV accumulation.
// ---------------------------------------------------------------------------
__global__ __launch_bounds__(256) void attn_kernel()
{
    extern __shared__ float sm[];
    float* Qt   = sm;                // [64][68]  d-major: Qt[d][t]
    float* Kt   = Qt + 64*68;        // [64][68]  d-major: Kt[d][s]
    float* St   = Kt + 64*68;        // [64][68]  s-major: St[s][t]
    float* Vs   = St + 64*68;        // [64][64]  s-major: Vs[s][d]
    float* mrow = Vs + 64*64;        // [64]
    float* lrow = mrow + 64;         // [64]
    float* arow = lrow + 64;         // [64]

    const int b_ = blockIdx.x, h = blockIdx.y, tc = blockIdx.z;
    const int tid = threadIdx.x;
    const int tx = tid & 15, ty = tid >> 4;

    const float* Qg = &g_Q[((b_*NHH + h)*TT + tc*64)*DHH];
    const float* Kg = &g_K[(b_*NHH + h)*TT*DHH];
    const float* Vg = &g_V[(b_*NHH + h)*TT*DHH];
    const float* Pg = &g_P[((b_*NHH + h)*TT + tc*64)*TT];

    // Load Q transposed into Qt[d][t]
    for (int idx = tid; idx < 1024; idx += 256) {
        const int r  = idx & 63;
        const int c4 = (idx >> 6) * 4;
        float4 v = *(const float4*)&Qg[r*64 + c4];
        Qt[(c4+0)*68 + r] = v.x;
        Qt[(c4+1)*68 + r] = v.y;
        Qt[(c4+2)*68 + r] = v.z;
        Qt[(c4+3)*68 + r] = v.w;
    }
    if (tid < 64) { mrow[tid] = -INFINITY; lrow[tid] = 0.f; }
    float acc[4][4];
    #pragma unroll
    for (int i = 0; i < 4; i++)
        #pragma unroll
        for (int j = 0; j < 4; j++) acc[i][j] = 0.f;
    __syncthreads();

    for (int sc = 0; sc < 8; sc++) {
        // Load K chunk transposed, V chunk natural
        const float* Kc = Kg + sc*64*64;
        for (int idx = tid; idx < 1024; idx += 256) {
            const int r  = idx & 63;
            const int c4 = (idx >> 6) * 4;
            float4 v = *(const float4*)&Kc[r*64 + c4];
            Kt[(c4+0)*68 + r] = v.x;
            Kt[(c4+1)*68 + r] = v.y;
            Kt[(c4+2)*68 + r] = v.z;
            Kt[(c4+3)*68 + r] = v.w;
        }
        const float4* Vc = (const float4*)(Vg + sc*64*64);
        for (int idx = tid; idx < 1024; idx += 256)
            ((float4*)Vs)[idx] = Vc[idx];
        __syncthreads();

        // Scores: position (from g_P) + content (Qt . Kt)
        float s4[4][4];
        #pragma unroll
        for (int i = 0; i < 4; i++) {
            float4 pv = *(const float4*)&Pg[(ty*4 + i)*TT + sc*64 + tx*4];
            s4[i][0]=pv.x; s4[i][1]=pv.y; s4[i][2]=pv.z; s4[i][3]=pv.w;
        }
        #pragma unroll 4
        for (int d = 0; d < 64; d++) {
            float4 qv = *(const float4*)&Qt[d*68 + ty*4];
            float4 kv = *(const float4*)&Kt[d*68 + tx*4];
            float qa[4] = {qv.x,qv.y,qv.z,qv.w};
            float ka[4] = {kv.x,kv.y,kv.z,kv.w};
            #pragma unroll
            for (int i = 0; i < 4; i++)
                #pragma unroll
                for (int j = 0; j < 4; j++) s4[i][j] += qa[i]*ka[j];
        }
        #pragma unroll
        for (int i = 0; i < 4; i++)
            #pragma unroll
            for (int j = 0; j < 4; j++)
                St[(tx*4 + j)*68 + ty*4 + i] = s4[i][j];
        __syncthreads();

        // Online softmax row update (thread t handles row t via St[s][t])
        if (tid < 64) {
            const float mo = mrow[tid];
            float mx = mo;
            #pragma unroll 8
            for (int s = 0; s < 64; s++) mx = fmaxf(mx, St[s*68 + tid]);
            const float al = __expf(mo - mx);
            float sum = 0.f;
            #pragma unroll 8
            for (int s = 0; s < 64; s++) {
                const float p = __expf(St[s*68 + tid] - mx);
                St[s*68 + tid] = p;
                sum += p;
            }
            mrow[tid] = mx;
            lrow[tid] = lrow[tid]*al + sum;
            arow[tid] = al;
        }
        __syncthreads();

        // Rescale accumulators, then PV
        float al4[4];
        #pragma unroll
        for (int i = 0; i < 4; i++) al4[i] = arow[ty*4 + i];
        #pragma unroll
        for (int i = 0; i < 4; i++)
            #pragma unroll
            for (int j = 0; j < 4; j++) acc[i][j] *= al4[i];
        #pragma unroll 4
        for (int s = 0; s < 64; s++) {
            float4 pv = *(const float4*)&St[s*68 + ty*4];
            float4 vv = *(const float4*)&Vs[s*64 + tx*4];
            float pa[4] = {pv.x,pv.y,pv.z,pv.w};
            float va[4] = {vv.x,vv.y,vv.z,vv.w};
            #pragma unroll
            for (int i = 0; i < 4; i++)
                #pragma unroll
                for (int j = 0; j < 4; j++) acc[i][j] += pa[i]*va[j];
        }
        __syncthreads();
    }

    // Write context [B,T,D]
    #pragma unroll
    for (int i = 0; i < 4; i++) {
        const int t_g = tc*64 + ty*4 + i;
        const float inv = 1.f / lrow[ty*4 + i];
        float4 o;
        o.x = acc[i][0]*inv; o.y = acc[i][1]*inv;
        o.z = acc[i][2]*inv; o.w = acc[i][3]*inv;
        *(float4*)&g_ctx[(b_*TT + t_g)*DM + h*DHH + tx*4] = o;
    }
}

// ---------------------------------------------------------------------------
// Output projection: d_out = g_ctx @ Wo^T + bo
// ---------------------------------------------------------------------------
__global__ __launch_bounds__(256) void out_gemm(
    float* __restrict__ out, const float* __restrict__ Wo, const float* __restrict__ bo)
{
    __shared__ float As[8][132];
    __shared__ float Bsm[8][132];

    const int tid = threadIdx.x;
    const int tx = tid & 15, ty = tid >> 4;
    const int m0 = blockIdx.x * 128;
    const int n0 = blockIdx.y * 128;
    const int lrow = tid >> 1;
    const int lcol = (tid & 1) * 4;

    float acc[8][8];
    #pragma unroll
    for (int i = 0; i < 8; i++)
        #pragma unroll
        for (int j = 0; j < 8; j++) acc[i][j] = 0.f;

    const float* Ap = &g_ctx[(m0 + lrow) * DM + lcol];
    const float* Bp = &Wo[(n0 + lrow) * DM + lcol];

    for (int k0 = 0; k0 < DM; k0 += 8) {
        float4 av  = *(const float4*)(Ap + k0);
        float4 bv4 = *(const float4*)(Bp + k0);
        __syncthreads();
        As[lcol+0][lrow]=av.x;  As[lcol+1][lrow]=av.y;  As[lcol+2][lrow]=av.z;  As[lcol+3][lrow]=av.w;
        Bsm[lcol+0][lrow]=bv4.x;Bsm[lcol+1][lrow]=bv4.y;Bsm[lcol+2][lrow]=bv4.z;Bsm[lcol+3][lrow]=bv4.w;
        __syncthreads();
        #pragma unroll
        for (int kk = 0; kk < 8; kk++) {
            float4 a0 = *(const float4*)&As[kk][ty*4];
            float4 a1 = *(const float4*)&As[kk][ty*4 + 64];
            float4 b0 = *(const float4*)&Bsm[kk][tx*4];
            float4 b1 = *(const float4*)&Bsm[kk][tx*4 + 64];
            float a[8] = {a0.x,a0.y,a0.z,a0.w,a1.x,a1.y,a1.z,a1.w};
            float b[8] = {b0.x,b0.y,b0.z,b0.w,b1.x,b1.y,b1.z,b1.w};
            #pragma unroll
            for (int i = 0; i < 8; i++)
                #pragma unroll
                for (int j = 0; j < 8; j++) acc[i][j] += a[i]*b[j];
        }
    }

    #pragma unroll
    for (int jg = 0; jg < 2; jg++) {
        const int nb = n0 + jg*64 + tx*4;
        const float4 bsv = *(const float4*)&bo[nb];
        #pragma unroll
        for (int i = 0; i < 8; i++) {
            const int r = m0 + ((i < 4) ? (ty*4 + i) : (64 + ty*4 + i - 4));
            float4 o;
            o.x = acc[i][jg*4+0] + bsv.x;
            o.y = acc[i][jg*4+1] + bsv.y;
            o.z = acc[i][jg*4+2] + bsv.z;
            o.w = acc[i][jg*4+3] + bsv.w;
            *(float4*)&out[r*DM + nb] = o;
        }
    }
}

// ---------------------------------------------------------------------------
extern "C" void kernel_launch(void* const* d_in, const int* in_sizes, int n_in,
                              void* d_out, int out_size)
{
    const float* x   = (const float*)d_in[0];
    const float* rel = (const float*)d_in[1];
    const float* Wq  = (const float*)d_in[2];
    const float* bq  = (const float*)d_in[3];
    const float* Wk  = (const float*)d_in[4];
    const float* bk  = (const float*)d_in[5];
    const float* Wv  = (const float*)d_in[6];
    const float* bv  = (const float*)d_in[7];
    const float* Wo  = (const float*)d_in[8];
    const float* bo  = (const float*)d_in[9];

    (void)in_sizes; (void)n_in; (void)out_size;

    cudaFuncSetAttribute(attn_kernel, cudaFuncAttributeMaxDynamicSharedMemorySize, 71680);

    qkv_gemm<<<dim3(32, 4, 3), 256>>>(x, Wq, bq, Wk, bk, Wv, bv);
    pos_kernel<<<dim3(512, 8), 128>>>(rel);
    attn_kernel<<<dim3(8, 8, 8), 256, 17344*4>>>();
    out_gemm<<<dim3(32, 4), 256>>>((float*)d_out, Wo, bo);
}

// round 3
// speedup vs baseline: 1.3158x; 1.3158x over previous
#include <cuda_runtime.h>
#include <cuda_bf16.h>
#include <math.h>
#include <stdint.h>

#define BB  8
#define TT  512
#define DM  512
#define NHH 8
#define DHH 64

// ---------------------------------------------------------------------------
// Scratch (static __device__ — no allocations allowed)
// ---------------------------------------------------------------------------
__device__ float g_Q[BB*NHH*TT*DHH];     // [B,NH,T,DH], pre-scaled by 1/8
__device__ float g_K[BB*NHH*TT*DHH];
__device__ float g_V[BB*NHH*TT*DHH];
__device__ float g_P[BB*NHH*TT*TT];      // position scores [B,NH,T,T]
__device__ float g_ctx[BB*TT*DM];        // attention context [B,T,D]
__device__ __nv_bfloat16 g_Ahi[BB*TT*DM];   // activation hi (x, then ctx)
__device__ __nv_bfloat16 g_Alo[BB*TT*DM];   // activation lo
__device__ __nv_bfloat16 g_Whi[4*DM*DM];    // Wq,Wk,Wv,Wo hi
__device__ __nv_bfloat16 g_Wlo[4*DM*DM];    // Wq,Wk,Wv,Wo lo

// ---------------------------------------------------------------------------
// mma.sync helpers (baseline sm_80+ features; compile for plain sm_103)
// ---------------------------------------------------------------------------
__device__ __forceinline__ uint32_t smem_u32(const void* p) {
    uint32_t a;
    asm("{ .reg .u64 t; cvta.to.shared.u64 t, %1; cvt.u32.u64 %0, t; }" : "=r"(a) : "l"(p));
    return a;
}
__device__ __forceinline__ void ldm_x4(uint32_t* r, uint32_t addr) {
    asm volatile("ldmatrix.sync.aligned.m8n8.x4.shared.b16 {%0,%1,%2,%3}, [%4];"
        : "=r"(r[0]), "=r"(r[1]), "=r"(r[2]), "=r"(r[3]) : "r"(addr));
}
__device__ __forceinline__ void mma_bf16(float* d, const uint32_t* a, const uint32_t* b) {
    asm volatile("mma.sync.aligned.m16n8k16.row.col.f32.bf16.bf16.f32 "
        "{%0,%1,%2,%3}, {%4,%5,%6,%7}, {%8,%9}, {%0,%1,%2,%3};"
        : "+f"(d[0]), "+f"(d[1]), "+f"(d[2]), "+f"(d[3])
        : "r"(a[0]), "r"(a[1]), "r"(a[2]), "r"(a[3]), "r"(b[0]), "r"(b[1]));
}

// ---------------------------------------------------------------------------
// fp32 -> bf16 (hi, lo) split conversion
// ---------------------------------------------------------------------------
__global__ __launch_bounds__(256) void convert_split(
    const float* __restrict__ src, __nv_bfloat16* __restrict__ hi,
    __nv_bfloat16* __restrict__ lo, int n)
{
    const int n4 = n >> 2;
    for (int i = blockIdx.x * blockDim.x + threadIdx.x; i < n4; i += gridDim.x * blockDim.x) {
        float4 v = ((const float4*)src)[i];
        float f[4] = {v.x, v.y, v.z, v.w};
        unsigned short hb[4], lb[4];
        #pragma unroll
        for (int j = 0; j < 4; j++) {
            __nv_bfloat16 h = __float2bfloat16(f[j]);
            __nv_bfloat16 l = __float2bfloat16(f[j] - __bfloat162float(h));
            hb[j] = *reinterpret_cast<unsigned short*>(&h);
            lb[j] = *reinterpret_cast<unsigned short*>(&l);
        }
        ((ushort4*)hi)[i] = make_ushort4(hb[0], hb[1], hb[2], hb[3]);
        ((ushort4*)lo)[i] = make_ushort4(lb[0], lb[1], lb[2], lb[3]);
    }
}

// ---------------------------------------------------------------------------
// mma.sync split-bf16 GEMM: C[m,n] = sum_k A[m,k] * W[n,k]  (+bias)*scale
// MODE 0: z selects Q/K/V, head-major output. MODE 1: row-major to out ptr.
// 128x128 CTA tile, 8 warps (2x4), 64x32 per warp, BK=32, reg prefetch.
// ---------------------------------------------------------------------------
template<int MODE>
__global__ __launch_bounds__(256) void gemm_tc(
    const __nv_bfloat16* __restrict__ Ahi, const __nv_bfloat16* __restrict__ Alo,
    const __nv_bfloat16* __restrict__ Whi, const __nv_bfloat16* __restrict__ Wlo,
    const float* __restrict__ bias0, const float* __restrict__ bias1,
    const float* __restrict__ bias2, float* __restrict__ out_override)
{
    __shared__ __align__(16) __nv_bfloat16 As[2][128][40];   // [hi/lo][m][k]
    __shared__ __align__(16) __nv_bfloat16 Bs[2][128][40];   // [hi/lo][n][k]

    const int tid  = threadIdx.x;
    const int wid  = tid >> 5;
    const int lane = tid & 31;
    const int m0 = blockIdx.x * 128;
    const int n0 = blockIdx.y * 128;
    const int z  = blockIdx.z;

    const float* bias; float* outp; float scale;
    const __nv_bfloat16 *Wh, *Wl;
    if (MODE == 0) {
        bias  = (z == 0) ? bias0 : (z == 1) ? bias1 : bias2;
        outp  = (z == 0) ? g_Q : (z == 1) ? g_K : g_V;
        scale = (z == 0) ? 0.125f : 1.0f;
        Wh = Whi + (size_t)z * DM * DM;
        Wl = Wlo + (size_t)z * DM * DM;
    } else {
        bias = bias0; outp = out_override; scale = 1.0f;
        Wh = Whi; Wl = Wlo;
    }

    // Global load pattern: thread t loads row (t>>1), 16 contiguous bf16 at
    // col ((t&1)*16) as two uint4, per buffer.
    const int grow = tid >> 1;
    const int gcol = (tid & 1) * 16;
    const __nv_bfloat16* gA = Ahi + (size_t)(m0 + grow) * DM + gcol;
    const __nv_bfloat16* gAl= Alo + (size_t)(m0 + grow) * DM + gcol;
    const __nv_bfloat16* gB = Wh  + (size_t)(n0 + grow) * DM + gcol;
    const __nv_bfloat16* gBl= Wl  + (size_t)(n0 + grow) * DM + gcol;

    uint4 pAh[2], pAl[2], pBh[2], pBl[2];
    #define LOAD_REGS(kc) do { \
        const int off = (kc) * 32; \
        pAh[0] = *(const uint4*)(gA  + off); pAh[1] = *(const uint4*)(gA  + off + 8); \
        pAl[0] = *(const uint4*)(gAl + off); pAl[1] = *(const uint4*)(gAl + off + 8); \
        pBh[0] = *(const uint4*)(gB  + off); pBh[1] = *(const uint4*)(gB  + off + 8); \
        pBl[0] = *(const uint4*)(gBl + off); pBl[1] = *(const uint4*)(gBl + off + 8); \
    } while (0)

    float acc[4][4][4];
    #pragma unroll
    for (int i = 0; i < 4; i++)
        #pragma unroll
        for (int j = 0; j < 4; j++)
            #pragma unroll
            for (int v = 0; v < 4; v++) acc[i][j][v] = 0.f;

    // ldmatrix lane address components
    const int wm = (wid >> 2) * 64;        // warp m base (0/64)
    const int wn = (wid & 3) * 32;         // warp n base (0/32/64/96)
    const int ar = (lane & 7) + ((lane >> 3) & 1) * 8;   // A row-in-tile
    const int ak = ((lane >> 4) & 1) * 8;                // A k offset
    const int br = (lane & 7) + ((lane >> 4) & 1) * 8;   // B row-in-pair
    const int bk = ((lane >> 3) & 1) * 8;                // B k offset

    const uint32_t aBase = smem_u32(&As[0][0][0]);
    const uint32_t bBase = smem_u32(&Bs[0][0][0]);
    const uint32_t bufStride = 128 * 40 * 2;             // bytes per hi/lo buffer

    LOAD_REGS(0);

    for (int kc = 0; kc < 16; kc++) {
        __syncthreads();
        *(uint4*)&As[0][grow][gcol]     = pAh[0];
        *(uint4*)&As[0][grow][gcol + 8] = pAh[1];
        *(uint4*)&As[1][grow][gcol]     = pAl[0];
        *(uint4*)&As[1][grow][gcol + 8] = pAl[1];
        *(uint4*)&Bs[0][grow][gcol]     = pBh[0];
        *(uint4*)&Bs[0][grow][gcol + 8] = pBh[1];
        *(uint4*)&Bs[1][grow][gcol]     = pBl[0];
        *(uint4*)&Bs[1][grow][gcol + 8] = pBl[1];
        __syncthreads();

        if (kc < 15) LOAD_REGS(kc + 1);

        #pragma unroll
        for (int ks = 0; ks < 2; ks++) {
            uint32_t ah[4][4], al[4][4];
            #pragma unroll
            for (int mt = 0; mt < 4; mt++) {
                const uint32_t ao = (uint32_t)((wm + mt * 16 + ar) * 40 + ks * 16 + ak) * 2;
                ldm_x4(ah[mt], aBase + ao);
                ldm_x4(al[mt], aBase + bufStride + ao);
            }
            uint32_t bh[2][4], bl[2][4];
            #pragma unroll
            for (int p = 0; p < 2; p++) {
                const uint32_t bo = (uint32_t)((wn + p * 16 + br) * 40 + ks * 16 + bk) * 2;
                ldm_x4(bh[p], bBase + bo);
                ldm_x4(bl[p], bBase + bufStride + bo);
            }
            #pragma unroll
            for (int mt = 0; mt < 4; mt++)
                #pragma unroll
                for (int nt = 0; nt < 4; nt++) {
                    const int p = nt >> 1, o = (nt & 1) * 2;
                    mma_bf16(acc[mt][nt], ah[mt], &bh[p][o]);
                    mma_bf16(acc[mt][nt], ah[mt], &bl[p][o]);
                    mma_bf16(acc[mt][nt], al[mt], &bh[p][o]);
                }
        }
    }
    #undef LOAD_REGS

    // Epilogue: direct global writes (float2 per fragment half-row)
    #pragma unroll
    for (int mt = 0; mt < 4; mt++) {
        #pragma unroll
        for (int nt = 0; nt < 4; nt++) {
            const int col = n0 + wn + nt * 8 + 2 * (lane & 3);
            const float bx = bias[col], by = bias[col + 1];
            #pragma unroll
            for (int half = 0; half < 2; half++) {
                const int m = m0 + wm + mt * 16 + (lane >> 2) + half * 8;
                float2 o;
                o.x = (acc[mt][nt][half * 2 + 0] + bx) * scale;
                o.y = (acc[mt][nt][half * 2 + 1] + by) * scale;
                if (MODE == 0) {
                    const int b_ = m >> 9, t = m & 511, h = col >> 6, d = col & 63;
                    *(float2*)&outp[(((size_t)b_ * NHH + h) * TT + t) * DHH + d] = o;
                } else {
                    *(float2*)&outp[(size_t)m * DM + col] = o;
                }
            }
        }
    }
}

// ---------------------------------------------------------------------------
// Position kernel: P[b,h,t,s] = Q[b,h,t,:] . rel_emb[t,s,h*64:...]
// ---------------------------------------------------------------------------
__global__ __launch_bounds__(128) void pos_kernel(const float* __restrict__ rel)
{
    const int t = blockIdx.x;
    const int h = blockIdx.y;
    const int tid  = threadIdx.x;
    const int lane = tid & 31;
    const int warp = tid >> 5;
    const int grp  = lane >> 3;
    const int dl   = lane & 7;

    float q[8][8];
    #pragma unroll
    for (int b_ = 0; b_ < 8; b_++) {
        const float* qp = &g_Q[((b_*NHH + h)*TT + t)*DHH + dl*8];
        float4 q0 = *(const float4*)qp;
        float4 q1 = *(const float4*)(qp + 4);
        q[b_][0]=q0.x; q[b_][1]=q0.y; q[b_][2]=q0.z; q[b_][3]=q0.w;
        q[b_][4]=q1.x; q[b_][5]=q1.y; q[b_][6]=q1.z; q[b_][7]=q1.w;
    }

    for (int s = warp*4 + grp; s < TT; s += 16) {
        const float* rp = &rel[(size_t)(t*TT + s)*DM + h*DHH + dl*8];
        float4 r0 = *(const float4*)rp;
        float4 r1 = *(const float4*)(rp + 4);
        float rv[8] = {r0.x,r0.y,r0.z,r0.w,r1.x,r1.y,r1.z,r1.w};
        float sum[8];
        #pragma unroll
        for (int b_ = 0; b_ < 8; b_++) {
            float a = 0.f;
            #pragma unroll
            for (int d = 0; d < 8; d++) a += q[b_][d] * rv[d];
            sum[b_] = a;
        }
        #pragma unroll
        for (int b_ = 0; b_ < 8; b_++) {
            sum[b_] += __shfl_xor_sync(0xffffffffu, sum[b_], 4);
            sum[b_] += __shfl_xor_sync(0xffffffffu, sum[b_], 2);
            sum[b_] += __shfl_xor_sync(0xffffffffu, sum[b_], 1);
        }
        float outv = sum[0];
        #pragma unroll
        for (int b_ = 1; b_ < 8; b_++) if (dl == b_) outv = sum[b_];
        g_P[(((size_t)dl*NHH + h)*TT + t)*TT + s] = outv;
    }
}

// ---------------------------------------------------------------------------
// Flash-style attention: per (b, h, 64-row t-chunk).
// ---------------------------------------------------------------------------
__global__ __launch_bounds__(256) void attn_kernel()
{
    extern __shared__ float sm[];
    float* Qt   = sm;                // [64][68]
    float* Kt   = Qt + 64*68;        // [64][68]
    float* St   = Kt + 64*68;        // [64][68]
    float* Vs   = St + 64*68;        // [64][64]
    float* mrow = Vs + 64*64;
    float* lrow = mrow + 64;
    float* arow = lrow + 64;

    const int b_ = blockIdx.x, h = blockIdx.y, tc = blockIdx.z;
    const int tid = threadIdx.x;
    const int tx = tid & 15, ty = tid >> 4;

    const float* Qg = &g_Q[((b_*NHH + h)*TT + tc*64)*DHH];
    const float* Kg = &g_K[(b_*NHH + h)*TT*DHH];
    const float* Vg = &g_V[(b_*NHH + h)*TT*DHH];
    const float* Pg = &g_P[(((size_t)b_*NHH + h)*TT + tc*64)*TT];

    for (int idx = tid; idx < 1024; idx += 256) {
        const int r  = idx & 63;
        const int c4 = (idx >> 6) * 4;
        float4 v = *(const float4*)&Qg[r*64 + c4];
        Qt[(c4+0)*68 + r] = v.x;
        Qt[(c4+1)*68 + r] = v.y;
        Qt[(c4+2)*68 + r] = v.z;
        Qt[(c4+3)*68 + r] = v.w;
    }
    if (tid < 64) { mrow[tid] = -INFINITY; lrow[tid] = 0.f; }
    float acc[4][4];
    #pragma unroll
    for (int i = 0; i < 4; i++)
        #pragma unroll
        for (int j = 0; j < 4; j++) acc[i][j] = 0.f;
    __syncthreads();

    for (int sc = 0; sc < 8; sc++) {
        const float* Kc = Kg + sc*64*64;
        for (int idx = tid; idx < 1024; idx += 256) {
            const int r  = idx & 63;
            const int c4 = (idx >> 6) * 4;
            float4 v = *(const float4*)&Kc[r*64 + c4];
            Kt[(c4+0)*68 + r] = v.x;
            Kt[(c4+1)*68 + r] = v.y;
            Kt[(c4+2)*68 + r] = v.z;
            Kt[(c4+3)*68 + r] = v.w;
        }
        const float4* Vc = (const float4*)(Vg + sc*64*64);
        for (int idx = tid; idx < 1024; idx += 256)
            ((float4*)Vs)[idx] = Vc[idx];
        __syncthreads();

        float s4[4][4];
        #pragma unroll
        for (int i = 0; i < 4; i++) {
            float4 pv = *(const float4*)&Pg[(ty*4 + i)*TT + sc*64 + tx*4];
            s4[i][0]=pv.x; s4[i][1]=pv.y; s4[i][2]=pv.z; s4[i][3]=pv.w;
        }
        #pragma unroll 4
        for (int d = 0; d < 64; d++) {
            float4 qv = *(const float4*)&Qt[d*68 + ty*4];
            float4 kv = *(const float4*)&Kt[d*68 + tx*4];
            float qa[4] = {qv.x,qv.y,qv.z,qv.w};
            float ka[4] = {kv.x,kv.y,kv.z,kv.w};
            #pragma unroll
            for (int i = 0; i < 4; i++)
                #pragma unroll
                for (int j = 0; j < 4; j++) s4[i][j] += qa[i]*ka[j];
        }
        #pragma unroll
        for (int i = 0; i < 4; i++)
            #pragma unroll
            for (int j = 0; j < 4; j++)
                St[(tx*4 + j)*68 + ty*4 + i] = s4[i][j];
        __syncthreads();

        if (tid < 64) {
            const float mo = mrow[tid];
            float mx = mo;
            #pragma unroll 8
            for (int s = 0; s < 64; s++) mx = fmaxf(mx, St[s*68 + tid]);
            const float al = __expf(mo - mx);
            float sum = 0.f;
            #pragma unroll 8
            for (int s = 0; s < 64; s++) {
                const float p = __expf(St[s*68 + tid] - mx);
                St[s*68 + tid] = p;
                sum += p;
            }
            mrow[tid] = mx;
            lrow[tid] = lrow[tid]*al + sum;
            arow[tid] = al;
        }
        __syncthreads();

        float al4[4];
        #pragma unroll
        for (int i = 0; i < 4; i++) al4[i] = arow[ty*4 + i];
        #pragma unroll
        for (int i = 0; i < 4; i++)
            #pragma unroll
            for (int j = 0; j < 4; j++) acc[i][j] *= al4[i];
        #pragma unroll 4
        for (int s = 0; s < 64; s++) {
            float4 pv = *(const float4*)&St[s*68 + ty*4];
            float4 vv = *(const float4*)&Vs[s*64 + tx*4];
            float pa[4] = {pv.x,pv.y,pv.z,pv.w};
            float va[4] = {vv.x,vv.y,vv.z,vv.w};
            #pragma unroll
            for (int i = 0; i < 4; i++)
                #pragma unroll
                for (int j = 0; j < 4; j++) acc[i][j] += pa[i]*va[j];
        }
        __syncthreads();
    }

    #pragma unroll
    for (int i = 0; i < 4; i++) {
        const int t_g = tc*64 + ty*4 + i;
        const float inv = 1.f / lrow[ty*4 + i];
        float4 o;
        o.x = acc[i][0]*inv; o.y = acc[i][1]*inv;
        o.z = acc[i][2]*inv; o.w = acc[i][3]*inv;
        *(float4*)&g_ctx[(b_*TT + t_g)*DM + h*DHH + tx*4] = o;
    }
}

// ---------------------------------------------------------------------------
extern "C" void kernel_launch(void* const* d_in, const int* in_sizes, int n_in,
                              void* d_out, int out_size)
{
    const float* x   = (const float*)d_in[0];
    const float* rel = (const float*)d_in[1];
    const float* Wq  = (const float*)d_in[2];
    const float* bq  = (const float*)d_in[3];
    const float* Wk  = (const float*)d_in[4];
    const float* bk  = (const float*)d_in[5];
    const float* Wv  = (const float*)d_in[6];
    const float* bv  = (const float*)d_in[7];
    const float* Wo  = (const float*)d_in[8];
    const float* bo  = (const float*)d_in[9];

    (void)in_sizes; (void)n_in; (void)out_size;

    cudaFuncSetAttribute(attn_kernel, cudaFuncAttributeMaxDynamicSharedMemorySize, 71680);

    // Resolve __device__ scratch addresses
    __nv_bfloat16 *pAhi, *pAlo, *pWhi, *pWlo;
    cudaGetSymbolAddress((void**)&pAhi, g_Ahi);
    cudaGetSymbolAddress((void**)&pAlo, g_Alo);
    cudaGetSymbolAddress((void**)&pWhi, g_Whi);
    cudaGetSymbolAddress((void**)&pWlo, g_Wlo);
    float* pctx;
    cudaGetSymbolAddress((void**)&pctx, g_ctx);

    // fp32 -> bf16 hi/lo splits
    convert_split<<<1024, 256>>>(x,  pAhi, pAlo, BB*TT*DM);
    convert_split<<<256,  256>>>(Wq, pWhi + 0*DM*DM, pWlo + 0*DM*DM, DM*DM);
    convert_split<<<256,  256>>>(Wk, pWhi + 1*DM*DM, pWlo + 1*DM*DM, DM*DM);
    convert_split<<<256,  256>>>(Wv, pWhi + 2*DM*DM, pWlo + 2*DM*DM, DM*DM);
    convert_split<<<256,  256>>>(Wo, pWhi + 3*DM*DM, pWlo + 3*DM*DM, DM*DM);

    // QKV projections on tensor cores (mma.sync)
    gemm_tc<0><<<dim3(32, 4, 3), 256>>>(pAhi, pAlo, pWhi, pWlo, bq, bk, bv, nullptr);

    pos_kernel<<<dim3(512, 8), 128>>>(rel);
    attn_kernel<<<dim3(8, 8, 8), 256, 17344*4>>>();

    // ctx -> bf16, output projection on tensor cores
    convert_split<<<1024, 256>>>(pctx, pAhi, pAlo, BB*TT*DM);
    gemm_tc<1><<<dim3(32, 4, 1), 256>>>(pAhi, pAlo, pWhi + 3*DM*DM, pWlo + 3*DM*DM,
                                        bo, nullptr, nullptr, (float*)d_out);
}

// round 4
// speedup vs baseline: 1.7861x; 1.3574x over previous
#include <cuda_runtime.h>
#include <cuda_bf16.h>
#include <math.h>
#include <stdint.h>

#define BB  8
#define TT  512
#define DM  512
#define NHH 8
#define DHH 64

// ---------------------------------------------------------------------------
// Scratch (static __device__ — no allocations allowed)
// ---------------------------------------------------------------------------
__device__ float g_Q[BB*NHH*TT*DHH];        // [B,NH,T,DH] fp32 (pos_kernel input)
__device__ float g_P[BB*NHH*TT*TT];         // position scores [B,NH,T,T]
__device__ float g_ctx[BB*TT*DM];           // attention context [B,T,D]
__device__ __nv_bfloat16 g_Ahi[BB*TT*DM];   // activation hi (x, then ctx)
__device__ __nv_bfloat16 g_Alo[BB*TT*DM];   // activation lo
__device__ __nv_bfloat16 g_Whi[4*DM*DM];    // Wq,Wk,Wv,Wo hi
__device__ __nv_bfloat16 g_Wlo[4*DM*DM];    // Wq,Wk,Wv,Wo lo
__device__ __nv_bfloat16 g_Qh[BB*NHH*TT*DHH], g_Ql[BB*NHH*TT*DHH];
__device__ __nv_bfloat16 g_Kh[BB*NHH*TT*DHH], g_Kl[BB*NHH*TT*DHH];
__device__ __nv_bfloat16 g_Vh[BB*NHH*TT*DHH], g_Vl[BB*NHH*TT*DHH];

// ---------------------------------------------------------------------------
// mma.sync helpers (baseline sm_80+ features; compile for plain sm_103)
// ---------------------------------------------------------------------------
__device__ __forceinline__ uint32_t smem_u32(const void* p) {
    uint32_t a;
    asm("{ .reg .u64 t; cvta.to.shared.u64 t, %1; cvt.u32.u64 %0, t; }" : "=r"(a) : "l"(p));
    return a;
}
__device__ __forceinline__ void ldm_x4(uint32_t* r, uint32_t addr) {
    asm volatile("ldmatrix.sync.aligned.m8n8.x4.shared.b16 {%0,%1,%2,%3}, [%4];"
        : "=r"(r[0]), "=r"(r[1]), "=r"(r[2]), "=r"(r[3]) : "r"(addr));
}
__device__ __forceinline__ void ldm_x4_trans(uint32_t* r, uint32_t addr) {
    asm volatile("ldmatrix.sync.aligned.m8n8.x4.trans.shared.b16 {%0,%1,%2,%3}, [%4];"
        : "=r"(r[0]), "=r"(r[1]), "=r"(r[2]), "=r"(r[3]) : "r"(addr));
}
__device__ __forceinline__ void mma_bf16(float* d, const uint32_t* a, const uint32_t* b) {
    asm volatile("mma.sync.aligned.m16n8k16.row.col.f32.bf16.bf16.f32 "
        "{%0,%1,%2,%3}, {%4,%5,%6,%7}, {%8,%9}, {%0,%1,%2,%3};"
        : "+f"(d[0]), "+f"(d[1]), "+f"(d[2]), "+f"(d[3])
        : "r"(a[0]), "r"(a[1]), "r"(a[2]), "r"(a[3]), "r"(b[0]), "r"(b[1]));
}
__device__ __forceinline__ uint32_t pack_bf16(float lo, float hi) {
    __nv_bfloat162 t = __floats2bfloat162_rn(lo, hi);
    return *reinterpret_cast<uint32_t*>(&t);
}

// ---------------------------------------------------------------------------
// fp32 -> bf16 (hi, lo) split conversion
// ---------------------------------------------------------------------------
__global__ __launch_bounds__(256) void convert_split(
    const float* __restrict__ src, __nv_bfloat16* __restrict__ hi,
    __nv_bfloat16* __restrict__ lo, int n)
{
    const int n4 = n >> 2;
    for (int i = blockIdx.x * blockDim.x + threadIdx.x; i < n4; i += gridDim.x * blockDim.x) {
        float4 v = ((const float4*)src)[i];
        float f[4] = {v.x, v.y, v.z, v.w};
        unsigned short hb[4], lb[4];
        #pragma unroll
        for (int j = 0; j < 4; j++) {
            __nv_bfloat16 h = __float2bfloat16(f[j]);
            __nv_bfloat16 l = __float2bfloat16(f[j] - __bfloat162float(h));
            hb[j] = *reinterpret_cast<unsigned short*>(&h);
            lb[j] = *reinterpret_cast<unsigned short*>(&l);
        }
        ((ushort4*)hi)[i] = make_ushort4(hb[0], hb[1], hb[2], hb[3]);
        ((ushort4*)lo)[i] = make_ushort4(lb[0], lb[1], lb[2], lb[3]);
    }
}

// ---------------------------------------------------------------------------
// mma.sync split-bf16 GEMM: C[m,n] = sum_k A[m,k] * W[n,k]  (+bias)*scale
// MODE 0: z selects Q/K/V; writes bf16 hi/lo head-major (+ fp32 Q for pos).
// MODE 1: row-major fp32 to out ptr.
// ---------------------------------------------------------------------------
template<int MODE>
__global__ __launch_bounds__(256) void gemm_tc(
    const __nv_bfloat16* __restrict__ Ahi, const __nv_bfloat16* __restrict__ Alo,
    const __nv_bfloat16* __restrict__ Whi, const __nv_bfloat16* __restrict__ Wlo,
    const float* __restrict__ bias0, const float* __restrict__ bias1,
    const float* __restrict__ bias2, float* __restrict__ out_override)
{
    __shared__ __align__(16) __nv_bfloat16 As[2][128][40];   // [hi/lo][m][k]
    __shared__ __align__(16) __nv_bfloat16 Bs[2][128][40];   // [hi/lo][n][k]

    const int tid  = threadIdx.x;
    const int wid  = tid >> 5;
    const int lane = tid & 31;
    const int m0 = blockIdx.x * 128;
    const int n0 = blockIdx.y * 128;
    const int z  = blockIdx.z;

    const float* bias; float scale;
    const __nv_bfloat16 *Wh, *Wl;
    __nv_bfloat16 *oh, *ol;
    if (MODE == 0) {
        bias  = (z == 0) ? bias0 : (z == 1) ? bias1 : bias2;
        scale = (z == 0) ? 0.125f : 1.0f;
        oh = (z == 0) ? g_Qh : (z == 1) ? g_Kh : g_Vh;
        ol = (z == 0) ? g_Ql : (z == 1) ? g_Kl : g_Vl;
        Wh = Whi + (size_t)z * DM * DM;
        Wl = Wlo + (size_t)z * DM * DM;
    } else {
        bias = bias0; scale = 1.0f;
        Wh = Whi; Wl = Wlo; oh = nullptr; ol = nullptr;
    }

    const int grow = tid >> 1;
    const int gcol = (tid & 1) * 16;
    const __nv_bfloat16* gA = Ahi + (size_t)(m0 + grow) * DM + gcol;
    const __nv_bfloat16* gAl= Alo + (size_t)(m0 + grow) * DM + gcol;
    const __nv_bfloat16* gB = Wh  + (size_t)(n0 + grow) * DM + gcol;
    const __nv_bfloat16* gBl= Wl  + (size_t)(n0 + grow) * DM + gcol;

    uint4 pAh[2], pAl[2], pBh[2], pBl[2];
    #define LOAD_REGS(kc) do { \
        const int off = (kc) * 32; \
        pAh[0] = *(const uint4*)(gA  + off); pAh[1] = *(const uint4*)(gA  + off + 8); \
        pAl[0] = *(const uint4*)(gAl + off); pAl[1] = *(const uint4*)(gAl + off + 8); \
        pBh[0] = *(const uint4*)(gB  + off); pBh[1] = *(const uint4*)(gB  + off + 8); \
        pBl[0] = *(const uint4*)(gBl + off); pBl[1] = *(const uint4*)(gBl + off + 8); \
    } while (0)

    float acc[4][4][4];
    #pragma unroll
    for (int i = 0; i < 4; i++)
        #pragma unroll
        for (int j = 0; j < 4; j++)
            #pragma unroll
            for (int v = 0; v < 4; v++) acc[i][j][v] = 0.f;

    const int wm = (wid >> 2) * 64;
    const int wn = (wid & 3) * 32;
    const int ar = (lane & 7) + ((lane >> 3) & 1) * 8;
    const int ak = ((lane >> 4) & 1) * 8;
    const int br = (lane & 7) + ((lane >> 4) & 1) * 8;
    const int bk = ((lane >> 3) & 1) * 8;

    const uint32_t aBase = smem_u32(&As[0][0][0]);
    const uint32_t bBase = smem_u32(&Bs[0][0][0]);
    const uint32_t bufStride = 128 * 40 * 2;

    LOAD_REGS(0);

    for (int kc = 0; kc < 16; kc++) {
        __syncthreads();
        *(uint4*)&As[0][grow][gcol]     = pAh[0];
        *(uint4*)&As[0][grow][gcol + 8] = pAh[1];
        *(uint4*)&As[1][grow][gcol]     = pAl[0];
        *(uint4*)&As[1][grow][gcol + 8] = pAl[1];
        *(uint4*)&Bs[0][grow][gcol]     = pBh[0];
        *(uint4*)&Bs[0][grow][gcol + 8] = pBh[1];
        *(uint4*)&Bs[1][grow][gcol]     = pBl[0];
        *(uint4*)&Bs[1][grow][gcol + 8] = pBl[1];
        __syncthreads();

        if (kc < 15) LOAD_REGS(kc + 1);

        #pragma unroll
        for (int ks = 0; ks < 2; ks++) {
            uint32_t ah[4][4], al[4][4];
            #pragma unroll
            for (int mt = 0; mt < 4; mt++) {
                const uint32_t ao = (uint32_t)((wm + mt * 16 + ar) * 40 + ks * 16 + ak) * 2;
                ldm_x4(ah[mt], aBase + ao);
                ldm_x4(al[mt], aBase + bufStride + ao);
            }
            uint32_t bh[2][4], bl[2][4];
            #pragma unroll
            for (int p = 0; p < 2; p++) {
                const uint32_t bo = (uint32_t)((wn + p * 16 + br) * 40 + ks * 16 + bk) * 2;
                ldm_x4(bh[p], bBase + bo);
                ldm_x4(bl[p], bBase + bufStride + bo);
            }
            #pragma unroll
            for (int mt = 0; mt < 4; mt++)
                #pragma unroll
                for (int nt = 0; nt < 4; nt++) {
                    const int p = nt >> 1, o = (nt & 1) * 2;
                    mma_bf16(acc[mt][nt], ah[mt], &bh[p][o]);
                    mma_bf16(acc[mt][nt], ah[mt], &bl[p][o]);
                    mma_bf16(acc[mt][nt], al[mt], &bh[p][o]);
                }
        }
    }
    #undef LOAD_REGS

    #pragma unroll
    for (int mt = 0; mt < 4; mt++) {
        #pragma unroll
        for (int nt = 0; nt < 4; nt++) {
            const int col = n0 + wn + nt * 8 + 2 * (lane & 3);
            const float bx = bias[col], by = bias[col + 1];
            #pragma unroll
            for (int half = 0; half < 2; half++) {
                const int m = m0 + wm + mt * 16 + (lane >> 2) + half * 8;
                float ox = (acc[mt][nt][half * 2 + 0] + bx) * scale;
                float oy = (acc[mt][nt][half * 2 + 1] + by) * scale;
                if (MODE == 0) {
                    const int b_ = m >> 9, t = m & 511, h = col >> 6, d = col & 63;
                    const size_t idx = (((size_t)b_ * NHH + h) * TT + t) * DHH + d;
                    __nv_bfloat16 hx = __float2bfloat16(ox);
                    __nv_bfloat16 hy = __float2bfloat16(oy);
                    __nv_bfloat16 lx = __float2bfloat16(ox - __bfloat162float(hx));
                    __nv_bfloat16 ly = __float2bfloat16(oy - __bfloat162float(hy));
                    *(__nv_bfloat162*)&oh[idx] = __nv_bfloat162(hx, hy);
                    *(__nv_bfloat162*)&ol[idx] = __nv_bfloat162(lx, ly);
                    if (z == 0) *(float2*)&g_Q[idx] = make_float2(ox, oy);
                } else {
                    *(float2*)&out_override[(size_t)m * DM + col] = make_float2(ox, oy);
                }
            }
        }
    }
}

// ---------------------------------------------------------------------------
// Position kernel: P[b,h,t,s] = Q[b,h,t,:] . rel_emb[t,s,h*64:...]
// ---------------------------------------------------------------------------
__global__ __launch_bounds__(128) void pos_kernel(const float* __restrict__ rel)
{
    const int t = blockIdx.x;
    const int h = blockIdx.y;
    const int tid  = threadIdx.x;
    const int lane = tid & 31;
    const int warp = tid >> 5;
    const int grp  = lane >> 3;
    const int dl   = lane & 7;

    float q[8][8];
    #pragma unroll
    for (int b_ = 0; b_ < 8; b_++) {
        const float* qp = &g_Q[((b_*NHH + h)*TT + t)*DHH + dl*8];
        float4 q0 = *(const float4*)qp;
        float4 q1 = *(const float4*)(qp + 4);
        q[b_][0]=q0.x; q[b_][1]=q0.y; q[b_][2]=q0.z; q[b_][3]=q0.w;
        q[b_][4]=q1.x; q[b_][5]=q1.y; q[b_][6]=q1.z; q[b_][7]=q1.w;
    }

    for (int s = warp*4 + grp; s < TT; s += 16) {
        const float* rp = &rel[(size_t)(t*TT + s)*DM + h*DHH + dl*8];
        float4 r0 = *(const float4*)rp;
        float4 r1 = *(const float4*)(rp + 4);
        float rv[8] = {r0.x,r0.y,r0.z,r0.w,r1.x,r1.y,r1.z,r1.w};
        float sum[8];
        #pragma unroll
        for (int b_ = 0; b_ < 8; b_++) {
            float a = 0.f;
            #pragma unroll
            for (int d = 0; d < 8; d++) a += q[b_][d] * rv[d];
            sum[b_] = a;
        }
        #pragma unroll
        for (int b_ = 0; b_ < 8; b_++) {
            sum[b_] += __shfl_xor_sync(0xffffffffu, sum[b_], 4);
            sum[b_] += __shfl_xor_sync(0xffffffffu, sum[b_], 2);
            sum[b_] += __shfl_xor_sync(0xffffffffu, sum[b_], 1);
        }
        float outv = sum[0];
        #pragma unroll
        for (int b_ = 1; b_ < 8; b_++) if (dl == b_) outv = sum[b_];
        g_P[(((size_t)dl*NHH + h)*TT + t)*TT + s] = outv;
    }
}

// ---------------------------------------------------------------------------
// Tensor-core flash attention. CTA = (tc, h, b): 128 q-rows, full 512 s loop
// in 64-chunks. 8 warps; warp w owns q rows [16w,16w+16) exclusively.
// S = P(fp32 init) + split-bf16 QK^T; online softmax in registers (quad
// shuffles only); P repacked in-register as A-frags (hi/lo); PV via
// ldmatrix.trans V (hi/lo), 3-term.
// ---------------------------------------------------------------------------
__global__ __launch_bounds__(256) void attn_tc()
{
    extern __shared__ __nv_bfloat16 smb[];
    __nv_bfloat16* Qh = smb;                 // [128][72]
    __nv_bfloat16* Ql = Qh + 128*72;
    __nv_bfloat16* Kh = Ql + 128*72;         // [64][72]
    __nv_bfloat16* Kl = Kh + 64*72;
    __nv_bfloat16* Vh = Kl + 64*72;          // [64][72]
    __nv_bfloat16* Vl = Vh + 64*72;

    const int tc = blockIdx.x, h = blockIdx.y, b_ = blockIdx.z;
    const int tid  = threadIdx.x;
    const int wid  = tid >> 5;
    const int lane = tid & 31;

    const size_t headoff = ((size_t)b_ * NHH + h) * TT * DHH;
    const __nv_bfloat16* gQh = g_Qh + headoff + (size_t)tc * 128 * DHH;
    const __nv_bfloat16* gQl = g_Ql + headoff + (size_t)tc * 128 * DHH;
    const __nv_bfloat16* gKh = g_Kh + headoff;
    const __nv_bfloat16* gKl = g_Kl + headoff;
    const __nv_bfloat16* gVh = g_Vh + headoff;
    const __nv_bfloat16* gVl = g_Vl + headoff;
    const float* Pg = g_P + (((size_t)b_ * NHH + h) * TT + tc * 128) * TT;

    // Load Q tile (128x64 bf16, hi+lo)
    #pragma unroll
    for (int it = 0; it < 4; it++) {
        const int idx = it * 256 + tid;         // 0..1023
        const int r = idx >> 3, c = (idx & 7) * 8;
        *(uint4*)&Qh[r * 72 + c] = *(const uint4*)&gQh[r * 64 + c];
        *(uint4*)&Ql[r * 72 + c] = *(const uint4*)&gQl[r * 64 + c];
    }

    const int wm = wid * 16;
    const int ar = (lane & 7) + ((lane >> 3) & 1) * 8;
    const int ak = ((lane >> 4) & 1) * 8;
    const int br = (lane & 7) + ((lane >> 4) & 1) * 8;
    const int bk = ((lane >> 3) & 1) * 8;
    const int vr = lane & 15;                  // trans: row = k0 + (lane&15)
    const int vc = ((lane >> 4) & 1) * 8;      // trans: col = d0 + this

    const uint32_t sQh = smem_u32(Qh), sQl = smem_u32(Ql);
    const uint32_t sKh = smem_u32(Kh), sKl = smem_u32(Kl);
    const uint32_t sVh = smem_u32(Vh), sVl = smem_u32(Vl);

    float acc_d[8][4];
    #pragma unroll
    for (int nt = 0; nt < 8; nt++)
        #pragma unroll
        for (int v = 0; v < 4; v++) acc_d[nt][v] = 0.f;
    float m_run[2] = {-INFINITY, -INFINITY};
    float l_run[2] = {0.f, 0.f};

    for (int sc = 0; sc < 8; sc++) {
        __syncthreads();
        // Load K,V chunk (64x64 bf16, hi+lo each)
        #pragma unroll
        for (int it = 0; it < 2; it++) {
            const int idx = it * 256 + tid;     // 0..511
            const int r = idx >> 3, c = (idx & 7) * 8;
            const int go = (sc * 64 + r) * 64 + c;
            *(uint4*)&Kh[r * 72 + c] = *(const uint4*)&gKh[go];
            *(uint4*)&Kl[r * 72 + c] = *(const uint4*)&gKl[go];
            *(uint4*)&Vh[r * 72 + c] = *(const uint4*)&gVh[go];
            *(uint4*)&Vl[r * 72 + c] = *(const uint4*)&gVl[go];
        }
        __syncthreads();

        // S accumulator init from position scores
        float acc_s[8][4];
        #pragma unroll
        for (int nt = 0; nt < 8; nt++) {
            const int scol = sc * 64 + nt * 8 + 2 * (lane & 3);
            #pragma unroll
            for (int half = 0; half < 2; half++) {
                const int trow = wm + (lane >> 2) + half * 8;
                float2 pv = *(const float2*)&Pg[(size_t)trow * TT + scol];
                acc_s[nt][half * 2 + 0] = pv.x;
                acc_s[nt][half * 2 + 1] = pv.y;
            }
        }

        // S += Qhi*Khi + Qhi*Klo + Qlo*Khi
        #pragma unroll
        for (int ks = 0; ks < 4; ks++) {
            uint32_t ah[4], al[4];
            const uint32_t ao = (uint32_t)((wm + ar) * 72 + ks * 16 + ak) * 2;
            ldm_x4(ah, sQh + ao);
            ldm_x4(al, sQl + ao);
            #pragma unroll
            for (int p = 0; p < 4; p++) {
                uint32_t bh[4], bl[4];
                const uint32_t bo = (uint32_t)((p * 16 + br) * 72 + ks * 16 + bk) * 2;
                ldm_x4(bh, sKh + bo);
                ldm_x4(bl, sKl + bo);
                #pragma unroll
                for (int q = 0; q < 2; q++) {
                    const int nt = p * 2 + q;
                    mma_bf16(acc_s[nt], ah, &bh[q * 2]);
                    mma_bf16(acc_s[nt], ah, &bl[q * 2]);
                    mma_bf16(acc_s[nt], al, &bh[q * 2]);
                }
            }
        }

        // Online softmax (warp-local rows; reduce across quad lanes)
        float alpha[2];
        #pragma unroll
        for (int half = 0; half < 2; half++) {
            float mx = m_run[half];
            #pragma unroll
            for (int nt = 0; nt < 8; nt++)
                mx = fmaxf(mx, fmaxf(acc_s[nt][half*2], acc_s[nt][half*2+1]));
            mx = fmaxf(mx, __shfl_xor_sync(0xffffffffu, mx, 1));
            mx = fmaxf(mx, __shfl_xor_sync(0xffffffffu, mx, 2));
            alpha[half] = __expf(m_run[half] - mx);
            float sum = 0.f;
            #pragma unroll
            for (int nt = 0; nt < 8; nt++) {
                float p0 = __expf(acc_s[nt][half*2]   - mx);
                float p1 = __expf(acc_s[nt][half*2+1] - mx);
                acc_s[nt][half*2]   = p0;
                acc_s[nt][half*2+1] = p1;
                sum += p0 + p1;
            }
            sum += __shfl_xor_sync(0xffffffffu, sum, 1);
            sum += __shfl_xor_sync(0xffffffffu, sum, 2);
            m_run[half] = mx;
            l_run[half] = l_run[half] * alpha[half] + sum;
        }
        #pragma unroll
        for (int nt = 0; nt < 8; nt++) {
            acc_d[nt][0] *= alpha[0]; acc_d[nt][1] *= alpha[0];
            acc_d[nt][2] *= alpha[1]; acc_d[nt][3] *= alpha[1];
        }

        // PV: repack P frags from acc_s (C-frag == A-frag layout), split hi/lo
        #pragma unroll
        for (int ks = 0; ks < 4; ks++) {
            uint32_t phi[4], plo[4];
            #pragma unroll
            for (int rr = 0; rr < 4; rr++) {
                const int nt = 2 * ks + (rr >> 1);
                const float p0 = acc_s[nt][(rr & 1) * 2 + 0];
                const float p1 = acc_s[nt][(rr & 1) * 2 + 1];
                const float h0 = __bfloat162float(__float2bfloat16(p0));
                const float h1 = __bfloat162float(__float2bfloat16(p1));
                phi[rr] = pack_bf16(h0, h1);
                plo[rr] = pack_bf16(p0 - h0, p1 - h1);
            }
            // reorder: a-frag = {r0c0, r1c0, r0c8, r1c8} -> phi built as
            // rr0={nt even, half0}, rr1={nt even, half1}, rr2={nt odd, half0}, rr3={nt odd, half1}
            // a[0]=row lo,k lo; a[1]=row hi,k lo; a[2]=row lo,k hi; a[3]=row hi,k hi
            uint32_t pa_h[4] = {phi[0], phi[1], phi[2], phi[3]};
            uint32_t pa_l[4] = {plo[0], plo[1], plo[2], plo[3]};
            #pragma unroll
            for (int dp = 0; dp < 4; dp++) {
                uint32_t vh[4], vl[4];
                const uint32_t vo = (uint32_t)((ks * 16 + vr) * 72 + dp * 16 + vc) * 2;
                ldm_x4_trans(vh, sVh + vo);
                ldm_x4_trans(vl, sVl + vo);
                #pragma unroll
                for (int q = 0; q < 2; q++) {
                    const int nt = dp * 2 + q;
                    mma_bf16(acc_d[nt], pa_h, &vh[q * 2]);
                    mma_bf16(acc_d[nt], pa_h, &vl[q * 2]);
                    mma_bf16(acc_d[nt], pa_l, &vh[q * 2]);
                }
            }
        }
    }

    // Final: divide by l and write context [B,T,D] (head-interleaved cols)
    const float inv0 = 1.f / l_run[0];
    const float inv1 = 1.f / l_run[1];
    #pragma unroll
    for (int nt = 0; nt < 8; nt++) {
        const int d = nt * 8 + 2 * (lane & 3);
        #pragma unroll
        for (int half = 0; half < 2; half++) {
            const int t_g = tc * 128 + wm + (lane >> 2) + half * 8;
            const float inv = half ? inv1 : inv0;
            float2 o;
            o.x = acc_d[nt][half * 2 + 0] * inv;
            o.y = acc_d[nt][half * 2 + 1] * inv;
            *(float2*)&g_ctx[((size_t)b_ * TT + t_g) * DM + h * DHH + d] = o;
        }
    }
}

// ---------------------------------------------------------------------------
extern "C" void kernel_launch(void* const* d_in, const int* in_sizes, int n_in,
                              void* d_out, int out_size)
{
    const float* x   = (const float*)d_in[0];
    const float* rel = (const float*)d_in[1];
    const float* Wq  = (const float*)d_in[2];
    const float* bq  = (const float*)d_in[3];
    const float* Wk  = (const float*)d_in[4];
    const float* bk  = (const float*)d_in[5];
    const float* Wv  = (const float*)d_in[6];
    const float* bv  = (const float*)d_in[7];
    const float* Wo  = (const float*)d_in[8];
    const float* bo  = (const float*)d_in[9];

    (void)in_sizes; (void)n_in; (void)out_size;

    cudaFuncSetAttribute(attn_tc, cudaFuncAttributeMaxDynamicSharedMemorySize, 73728);

    __nv_bfloat16 *pAhi, *pAlo, *pWhi, *pWlo;
    cudaGetSymbolAddress((void**)&pAhi, g_Ahi);
    cudaGetSymbolAddress((void**)&pAlo, g_Alo);
    cudaGetSymbolAddress((void**)&pWhi, g_Whi);
    cudaGetSymbolAddress((void**)&pWlo, g_Wlo);
    float* pctx;
    cudaGetSymbolAddress((void**)&pctx, g_ctx);

    // fp32 -> bf16 hi/lo splits
    convert_split<<<1024, 256>>>(x,  pAhi, pAlo, BB*TT*DM);
    convert_split<<<256,  256>>>(Wq, pWhi + 0*DM*DM, pWlo + 0*DM*DM, DM*DM);
    convert_split<<<256,  256>>>(Wk, pWhi + 1*DM*DM, pWlo + 1*DM*DM, DM*DM);
    convert_split<<<256,  256>>>(Wv, pWhi + 2*DM*DM, pWlo + 2*DM*DM, DM*DM);
    convert_split<<<256,  256>>>(Wo, pWhi + 3*DM*DM, pWlo + 3*DM*DM, DM*DM);

    // QKV projections on tensor cores (writes bf16 hi/lo + fp32 Q)
    gemm_tc<0><<<dim3(32, 4, 3), 256>>>(pAhi, pAlo, pWhi, pWlo, bq, bk, bv, nullptr);

    pos_kernel<<<dim3(512, 8), 128>>>(rel);
    attn_tc<<<dim3(4, 8, 8), 256, 73728>>>();

    // ctx -> bf16, output projection on tensor cores
    convert_split<<<1024, 256>>>(pctx, pAhi, pAlo, BB*TT*DM);
    gemm_tc<1><<<dim3(32, 4, 1), 256>>>(pAhi, pAlo, pWhi + 3*DM*DM, pWlo + 3*DM*DM,
                                        bo, nullptr, nullptr, (float*)d_out);
}

// round 5
// speedup vs baseline: 1.8593x; 1.0410x over previous
#include <cuda_runtime.h>
#include <cuda_bf16.h>
#include <math.h>
#include <stdint.h>

#define BB  8
#define TT  512
#define DM  512
#define NHH 8
#define DHH 64
#define LOG2E 1.4426950408889634f

// ---------------------------------------------------------------------------
// Scratch (static __device__ — no allocations allowed)
// ---------------------------------------------------------------------------
__device__ float g_Q[BB*NHH*TT*DHH];        // [B,NH,T,DH] fp32, scaled by log2e/8
__device__ float g_P[BB*NHH*TT*TT];         // position scores (log2 units)
__device__ float g_ctx[BB*TT*DM];           // attention context [B,T,D]
__device__ __nv_bfloat16 g_Ahi[BB*TT*DM];
__device__ __nv_bfloat16 g_Alo[BB*TT*DM];
__device__ __nv_bfloat16 g_Whi[4*DM*DM];
__device__ __nv_bfloat16 g_Wlo[4*DM*DM];
__device__ __nv_bfloat16 g_Qh[BB*NHH*TT*DHH], g_Ql[BB*NHH*TT*DHH];
__device__ __nv_bfloat16 g_Kh[BB*NHH*TT*DHH], g_Kl[BB*NHH*TT*DHH];
__device__ __nv_bfloat16 g_Vh[BB*NHH*TT*DHH], g_Vl[BB*NHH*TT*DHH];

// ---------------------------------------------------------------------------
// helpers
// ---------------------------------------------------------------------------
__device__ __forceinline__ uint32_t smem_u32(const void* p) {
    uint32_t a;
    asm("{ .reg .u64 t; cvta.to.shared.u64 t, %1; cvt.u32.u64 %0, t; }" : "=r"(a) : "l"(p));
    return a;
}
__device__ __forceinline__ void ldm_x4(uint32_t* r, uint32_t addr) {
    asm volatile("ldmatrix.sync.aligned.m8n8.x4.shared.b16 {%0,%1,%2,%3}, [%4];"
        : "=r"(r[0]), "=r"(r[1]), "=r"(r[2]), "=r"(r[3]) : "r"(addr));
}
__device__ __forceinline__ void ldm_x4_trans(uint32_t* r, uint32_t addr) {
    asm volatile("ldmatrix.sync.aligned.m8n8.x4.trans.shared.b16 {%0,%1,%2,%3}, [%4];"
        : "=r"(r[0]), "=r"(r[1]), "=r"(r[2]), "=r"(r[3]) : "r"(addr));
}
__device__ __forceinline__ void mma_bf16(float* d, const uint32_t* a, const uint32_t* b) {
    asm volatile("mma.sync.aligned.m16n8k16.row.col.f32.bf16.bf16.f32 "
        "{%0,%1,%2,%3}, {%4,%5,%6,%7}, {%8,%9}, {%0,%1,%2,%3};"
        : "+f"(d[0]), "+f"(d[1]), "+f"(d[2]), "+f"(d[3])
        : "r"(a[0]), "r"(a[1]), "r"(a[2]), "r"(a[3]), "r"(b[0]), "r"(b[1]));
}
__device__ __forceinline__ uint32_t pack_bf16(float lo, float hi) {
    __nv_bfloat162 t = __floats2bfloat162_rn(lo, hi);
    return *reinterpret_cast<uint32_t*>(&t);
}
__device__ __forceinline__ float ex2f(float x) {
    float r; asm("ex2.approx.ftz.f32 %0, %1;" : "=f"(r) : "f"(x)); return r;
}
#define CPASYNC16(daddr, sptr) \
    asm volatile("cp.async.cg.shared.global [%0], [%1], 16;" :: "r"(daddr), "l"(sptr) : "memory")
#define CPASYNC_COMMIT() asm volatile("cp.async.commit_group;" ::: "memory")
#define CPASYNC_WAIT1()  asm volatile("cp.async.wait_group 1;" ::: "memory")
#define CPASYNC_WAIT0()  asm volatile("cp.async.wait_group 0;" ::: "memory")

// ---------------------------------------------------------------------------
// fp32 -> bf16 (hi, lo) split conversion
// ---------------------------------------------------------------------------
__device__ __forceinline__ void split_store(const float* src, __nv_bfloat16* hi,
                                            __nv_bfloat16* lo, int i)
{
    float4 v = ((const float4*)src)[i];
    float f[4] = {v.x, v.y, v.z, v.w};
    unsigned short hb[4], lb[4];
    #pragma unroll
    for (int j = 0; j < 4; j++) {
        __nv_bfloat16 h = __float2bfloat16(f[j]);
        __nv_bfloat16 l = __float2bfloat16(f[j] - __bfloat162float(h));
        hb[j] = *reinterpret_cast<unsigned short*>(&h);
        lb[j] = *reinterpret_cast<unsigned short*>(&l);
    }
    ((ushort4*)hi)[i] = make_ushort4(hb[0], hb[1], hb[2], hb[3]);
    ((ushort4*)lo)[i] = make_ushort4(lb[0], lb[1], lb[2], lb[3]);
}

__global__ __launch_bounds__(256) void convert_split(
    const float* __restrict__ src, __nv_bfloat16* __restrict__ hi,
    __nv_bfloat16* __restrict__ lo, int n)
{
    const int n4 = n >> 2;
    for (int i = blockIdx.x * blockDim.x + threadIdx.x; i < n4; i += gridDim.x * blockDim.x)
        split_store(src, hi, lo, i);
}

// all four weight matrices in one launch (blockIdx.y selects)
__global__ __launch_bounds__(256) void convert_split_w(
    const float* __restrict__ w0, const float* __restrict__ w1,
    const float* __restrict__ w2, const float* __restrict__ w3,
    __nv_bfloat16* __restrict__ hi, __nv_bfloat16* __restrict__ lo)
{
    const int z = blockIdx.y;
    const float* src = (z == 0) ? w0 : (z == 1) ? w1 : (z == 2) ? w2 : w3;
    __nv_bfloat16* h = hi + (size_t)z * DM * DM;
    __nv_bfloat16* l = lo + (size_t)z * DM * DM;
    const int n4 = (DM * DM) >> 2;
    for (int i = blockIdx.x * blockDim.x + threadIdx.x; i < n4; i += gridDim.x * blockDim.x)
        split_store(src, h, l, i);
}

// ---------------------------------------------------------------------------
// mma.sync split-bf16 GEMM (unchanged structure from round 4)
// ---------------------------------------------------------------------------
template<int MODE>
__global__ __launch_bounds__(256) void gemm_tc(
    const __nv_bfloat16* __restrict__ Ahi, const __nv_bfloat16* __restrict__ Alo,
    const __nv_bfloat16* __restrict__ Whi, const __nv_bfloat16* __restrict__ Wlo,
    const float* __restrict__ bias0, const float* __restrict__ bias1,
    const float* __restrict__ bias2, float* __restrict__ out_override)
{
    __shared__ __align__(16) __nv_bfloat16 As[2][128][40];
    __shared__ __align__(16) __nv_bfloat16 Bs[2][128][40];

    const int tid  = threadIdx.x;
    const int wid  = tid >> 5;
    const int lane = tid & 31;
    const int m0 = blockIdx.x * 128;
    const int n0 = blockIdx.y * 128;
    const int z  = blockIdx.z;

    const float* bias; float scale;
    const __nv_bfloat16 *Wh, *Wl;
    __nv_bfloat16 *oh, *ol;
    if (MODE == 0) {
        bias  = (z == 0) ? bias0 : (z == 1) ? bias1 : bias2;
        scale = (z == 0) ? 0.125f * LOG2E : 1.0f;   // log2e folded into Q
        oh = (z == 0) ? g_Qh : (z == 1) ? g_Kh : g_Vh;
        ol = (z == 0) ? g_Ql : (z == 1) ? g_Kl : g_Vl;
        Wh = Whi + (size_t)z * DM * DM;
        Wl = Wlo + (size_t)z * DM * DM;
    } else {
        bias = bias0; scale = 1.0f;
        Wh = Whi; Wl = Wlo; oh = nullptr; ol = nullptr;
    }

    const int grow = tid >> 1;
    const int gcol = (tid & 1) * 16;
    const __nv_bfloat16* gA = Ahi + (size_t)(m0 + grow) * DM + gcol;
    const __nv_bfloat16* gAl= Alo + (size_t)(m0 + grow) * DM + gcol;
    const __nv_bfloat16* gB = Wh  + (size_t)(n0 + grow) * DM + gcol;
    const __nv_bfloat16* gBl= Wl  + (size_t)(n0 + grow) * DM + gcol;

    uint4 pAh[2], pAl[2], pBh[2], pBl[2];
    #define LOAD_REGS(kc) do { \
        const int off = (kc) * 32; \
        pAh[0] = *(const uint4*)(gA  + off); pAh[1] = *(const uint4*)(gA  + off + 8); \
        pAl[0] = *(const uint4*)(gAl + off); pAl[1] = *(const uint4*)(gAl + off + 8); \
        pBh[0] = *(const uint4*)(gB  + off); pBh[1] = *(const uint4*)(gB  + off + 8); \
        pBl[0] = *(const uint4*)(gBl + off); pBl[1] = *(const uint4*)(gBl + off + 8); \
    } while (0)

    float acc[4][4][4];
    #pragma unroll
    for (int i = 0; i < 4; i++)
        #pragma unroll
        for (int j = 0; j < 4; j++)
            #pragma unroll
            for (int v = 0; v < 4; v++) acc[i][j][v] = 0.f;

    const int wm = (wid >> 2) * 64;
    const int wn = (wid & 3) * 32;
    const int ar = (lane & 7) + ((lane >> 3) & 1) * 8;
    const int ak = ((lane >> 4) & 1) * 8;
    const int br = (lane & 7) + ((lane >> 4) & 1) * 8;
    const int bk = ((lane >> 3) & 1) * 8;

    const uint32_t aBase = smem_u32(&As[0][0][0]);
    const uint32_t bBase = smem_u32(&Bs[0][0][0]);
    const uint32_t bufStride = 128 * 40 * 2;

    LOAD_REGS(0);

    for (int kc = 0; kc < 16; kc++) {
        __syncthreads();
        *(uint4*)&As[0][grow][gcol]     = pAh[0];
        *(uint4*)&As[0][grow][gcol + 8] = pAh[1];
        *(uint4*)&As[1][grow][gcol]     = pAl[0];
        *(uint4*)&As[1][grow][gcol + 8] = pAl[1];
        *(uint4*)&Bs[0][grow][gcol]     = pBh[0];
        *(uint4*)&Bs[0][grow][gcol + 8] = pBh[1];
        *(uint4*)&Bs[1][grow][gcol]     = pBl[0];
        *(uint4*)&Bs[1][grow][gcol + 8] = pBl[1];
        __syncthreads();

        if (kc < 15) LOAD_REGS(kc + 1);

        #pragma unroll
        for (int ks = 0; ks < 2; ks++) {
            uint32_t ah[4][4], al[4][4];
            #pragma unroll
            for (int mt = 0; mt < 4; mt++) {
                const uint32_t ao = (uint32_t)((wm + mt * 16 + ar) * 40 + ks * 16 + ak) * 2;
                ldm_x4(ah[mt], aBase + ao);
                ldm_x4(al[mt], aBase + bufStride + ao);
            }
            uint32_t bh[2][4], bl[2][4];
            #pragma unroll
            for (int p = 0; p < 2; p++) {
                const uint32_t bo = (uint32_t)((wn + p * 16 + br) * 40 + ks * 16 + bk) * 2;
                ldm_x4(bh[p], bBase + bo);
                ldm_x4(bl[p], bBase + bufStride + bo);
            }
            #pragma unroll
            for (int mt = 0; mt < 4; mt++)
                #pragma unroll
                for (int nt = 0; nt < 4; nt++) {
                    const int p = nt >> 1, o = (nt & 1) * 2;
                    mma_bf16(acc[mt][nt], ah[mt], &bh[p][o]);
                    mma_bf16(acc[mt][nt], ah[mt], &bl[p][o]);
                    mma_bf16(acc[mt][nt], al[mt], &bh[p][o]);
                }
        }
    }
    #undef LOAD_REGS

    #pragma unroll
    for (int mt = 0; mt < 4; mt++) {
        #pragma unroll
        for (int nt = 0; nt < 4; nt++) {
            const int col = n0 + wn + nt * 8 + 2 * (lane & 3);
            const float bx = bias[col], by = bias[col + 1];
            #pragma unroll
            for (int half = 0; half < 2; half++) {
                const int m = m0 + wm + mt * 16 + (lane >> 2) + half * 8;
                float ox = (acc[mt][nt][half * 2 + 0] + bx) * scale;
                float oy = (acc[mt][nt][half * 2 + 1] + by) * scale;
                if (MODE == 0) {
                    const int b_ = m >> 9, t = m & 511, h = col >> 6, d = col & 63;
                    const size_t idx = (((size_t)b_ * NHH + h) * TT + t) * DHH + d;
                    __nv_bfloat16 hx = __float2bfloat16(ox);
                    __nv_bfloat16 hy = __float2bfloat16(oy);
                    __nv_bfloat16 lx = __float2bfloat16(ox - __bfloat162float(hx));
                    __nv_bfloat16 ly = __float2bfloat16(oy - __bfloat162float(hy));
                    *(__nv_bfloat162*)&oh[idx] = __nv_bfloat162(hx, hy);
                    *(__nv_bfloat162*)&ol[idx] = __nv_bfloat162(lx, ly);
                    if (z == 0) *(float2*)&g_Q[idx] = make_float2(ox, oy);
                } else {
                    *(float2*)&out_override[(size_t)m * DM + col] = make_float2(ox, oy);
                }
            }
        }
    }
}

// ---------------------------------------------------------------------------
// Position kernel: P[b,h,t,s] = Q[b,h,t,:] . rel_emb[t,s,h*64:...]
// (Q pre-scaled by log2e/8 -> P is in log2 units)
// ---------------------------------------------------------------------------
__global__ __launch_bounds__(128) void pos_kernel(const float* __restrict__ rel)
{
    const int t = blockIdx.x;
    const int h = blockIdx.y;
    const int tid  = threadIdx.x;
    const int lane = tid & 31;
    const int warp = tid >> 5;
    const int grp  = lane >> 3;
    const int dl   = lane & 7;

    float q[8][8];
    #pragma unroll
    for (int b_ = 0; b_ < 8; b_++) {
        const float* qp = &g_Q[((b_*NHH + h)*TT + t)*DHH + dl*8];
        float4 q0 = *(const float4*)qp;
        float4 q1 = *(const float4*)(qp + 4);
        q[b_][0]=q0.x; q[b_][1]=q0.y; q[b_][2]=q0.z; q[b_][3]=q0.w;
        q[b_][4]=q1.x; q[b_][5]=q1.y; q[b_][6]=q1.z; q[b_][7]=q1.w;
    }

    for (int s = warp*4 + grp; s < TT; s += 16) {
        const float* rp = &rel[(size_t)(t*TT + s)*DM + h*DHH + dl*8];
        float4 r0 = *(const float4*)rp;
        float4 r1 = *(const float4*)(rp + 4);
        float rv[8] = {r0.x,r0.y,r0.z,r0.w,r1.x,r1.y,r1.z,r1.w};
        float sum[8];
        #pragma unroll
        for (int b_ = 0; b_ < 8; b_++) {
            float a = 0.f;
            #pragma unroll
            for (int d = 0; d < 8; d++) a += q[b_][d] * rv[d];
            sum[b_] = a;
        }
        #pragma unroll
        for (int b_ = 0; b_ < 8; b_++) {
            sum[b_] += __shfl_xor_sync(0xffffffffu, sum[b_], 4);
            sum[b_] += __shfl_xor_sync(0xffffffffu, sum[b_], 2);
            sum[b_] += __shfl_xor_sync(0xffffffffu, sum[b_], 1);
        }
        float outv = sum[0];
        #pragma unroll
        for (int b_ = 1; b_ < 8; b_++) if (dl == b_) outv = sum[b_];
        g_P[(((size_t)dl*NHH + h)*TT + t)*TT + s] = outv;
    }
}

// ---------------------------------------------------------------------------
// Tensor-core flash attention with 3-stage cp.async K/V pipeline.
// CTA = (tc, h, b): 128 q-rows, 8 s-chunks of 64. Softmax in log2 units (ex2).
// ---------------------------------------------------------------------------
__global__ __launch_bounds__(256) void attn_tc()
{
    extern __shared__ __nv_bfloat16 smb[];
    // layout (bytes): Qh[0,18432) Ql[18432,36864) then 3 stages of
    // {Kh,Kl,Vh,Vl} each 9216 bytes (64x72 bf16) -> stage stride 36864
    __nv_bfloat16* Qh = smb;
    __nv_bfloat16* Ql = Qh + 128*72;

    const int tc = blockIdx.x, h = blockIdx.y, b_ = blockIdx.z;
    const int tid  = threadIdx.x;
    const int wid  = tid >> 5;
    const int lane = tid & 31;

    const size_t headoff = ((size_t)b_ * NHH + h) * TT * DHH;
    const __nv_bfloat16* gQh = g_Qh + headoff + (size_t)tc * 128 * DHH;
    const __nv_bfloat16* gQl = g_Ql + headoff + (size_t)tc * 128 * DHH;
    const __nv_bfloat16* gKh = g_Kh + headoff;
    const __nv_bfloat16* gKl = g_Kl + headoff;
    const __nv_bfloat16* gVh = g_Vh + headoff;
    const __nv_bfloat16* gVl = g_Vl + headoff;
    const float* Pg = g_P + (((size_t)b_ * NHH + h) * TT + tc * 128) * TT;

    const uint32_t sbase = smem_u32(smb);

    // Load Q tile (plain LDG/STS; covered by first barrier)
    #pragma unroll
    for (int it = 0; it < 4; it++) {
        const int idx = it * 256 + tid;
        const int r = idx >> 3, c = (idx & 7) * 8;
        *(uint4*)&Qh[r * 72 + c] = *(const uint4*)&gQh[r * 64 + c];
        *(uint4*)&Ql[r * 72 + c] = *(const uint4*)&gQl[r * 64 + c];
    }

    // cp.async prefetch of one 64-s chunk into stage st
    #define PREFETCH(sc_, st_) do { \
        const uint32_t so = sbase + 36864u + (uint32_t)(st_) * 36864u; \
        _Pragma("unroll") \
        for (int it = 0; it < 2; it++) { \
            const int idx = it * 256 + tid; \
            const int r = idx >> 3, c = (idx & 7) * 8; \
            const uint32_t d = (uint32_t)(r * 72 + c) * 2; \
            const size_t g = (size_t)((sc_) * 64 + r) * 64 + c; \
            CPASYNC16(so + d,          gKh + g); \
            CPASYNC16(so +  9216u + d, gKl + g); \
            CPASYNC16(so + 18432u + d, gVh + g); \
            CPASYNC16(so + 27648u + d, gVl + g); \
        } \
        CPASYNC_COMMIT(); \
    } while (0)

    const int wm = wid * 16;
    const int ar = (lane & 7) + ((lane >> 3) & 1) * 8;
    const int ak = ((lane >> 4) & 1) * 8;
    const int br = (lane & 7) + ((lane >> 4) & 1) * 8;
    const int bk = ((lane >> 3) & 1) * 8;
    const int vr = lane & 15;
    const int vc = ((lane >> 4) & 1) * 8;

    const uint32_t sQh = sbase, sQl = sbase + 18432u;

    float acc_d[8][4];
    #pragma unroll
    for (int nt = 0; nt < 8; nt++)
        #pragma unroll
        for (int v = 0; v < 4; v++) acc_d[nt][v] = 0.f;
    float m_run[2] = {-INFINITY, -INFINITY};
    float l_run[2] = {0.f, 0.f};

    PREFETCH(0, 0);

    for (int sc = 0; sc < 8; sc++) {
        const int st = sc % 3;
        if (sc < 7) { PREFETCH(sc + 1, (sc + 1) % 3); CPASYNC_WAIT1(); }
        else        { CPASYNC_WAIT0(); }
        __syncthreads();

        const uint32_t sKh = sbase + 36864u + (uint32_t)st * 36864u;
        const uint32_t sKl = sKh +  9216u;
        const uint32_t sVh = sKh + 18432u;
        const uint32_t sVl = sKh + 27648u;

        // S accumulator init from position scores (log2 units)
        float acc_s[8][4];
        #pragma unroll
        for (int nt = 0; nt < 8; nt++) {
            const int scol = sc * 64 + nt * 8 + 2 * (lane & 3);
            #pragma unroll
            for (int half = 0; half < 2; half++) {
                const int trow = wm + (lane >> 2) + half * 8;
                float2 pv = *(const float2*)&Pg[(size_t)trow * TT + scol];
                acc_s[nt][half * 2 + 0] = pv.x;
                acc_s[nt][half * 2 + 1] = pv.y;
            }
        }

        // S += Qhi*Khi + Qhi*Klo + Qlo*Khi
        #pragma unroll
        for (int ks = 0; ks < 4; ks++) {
            uint32_t ah[4], al[4];
            const uint32_t ao = (uint32_t)((wm + ar) * 72 + ks * 16 + ak) * 2;
            ldm_x4(ah, sQh + ao);
            ldm_x4(al, sQl + ao);
            #pragma unroll
            for (int p = 0; p < 4; p++) {
                uint32_t bh[4], bl[4];
                const uint32_t bo = (uint32_t)((p * 16 + br) * 72 + ks * 16 + bk) * 2;
                ldm_x4(bh, sKh + bo);
                ldm_x4(bl, sKl + bo);
                #pragma unroll
                for (int q = 0; q < 2; q++) {
                    const int nt = p * 2 + q;
                    mma_bf16(acc_s[nt], ah, &bh[q * 2]);
                    mma_bf16(acc_s[nt], ah, &bl[q * 2]);
                    mma_bf16(acc_s[nt], al, &bh[q * 2]);
                }
            }
        }

        // Online softmax in log2 units (quad shuffles only)
        float alpha[2];
        #pragma unroll
        for (int half = 0; half < 2; half++) {
            float mx = m_run[half];
            #pragma unroll
            for (int nt = 0; nt < 8; nt++)
                mx = fmaxf(mx, fmaxf(acc_s[nt][half*2], acc_s[nt][half*2+1]));
            mx = fmaxf(mx, __shfl_xor_sync(0xffffffffu, mx, 1));
            mx = fmaxf(mx, __shfl_xor_sync(0xffffffffu, mx, 2));
            alpha[half] = ex2f(m_run[half] - mx);
            float sum = 0.f;
            #pragma unroll
            for (int nt = 0; nt < 8; nt++) {
                float p0 = ex2f(acc_s[nt][half*2]   - mx);
                float p1 = ex2f(acc_s[nt][half*2+1] - mx);
                acc_s[nt][half*2]   = p0;
                acc_s[nt][half*2+1] = p1;
                sum += p0 + p1;
            }
            sum += __shfl_xor_sync(0xffffffffu, sum, 1);
            sum += __shfl_xor_sync(0xffffffffu, sum, 2);
            m_run[half] = mx;
            l_run[half] = l_run[half] * alpha[half] + sum;
        }
        #pragma unroll
        for (int nt = 0; nt < 8; nt++) {
            acc_d[nt][0] *= alpha[0]; acc_d[nt][1] *= alpha[0];
            acc_d[nt][2] *= alpha[1]; acc_d[nt][3] *= alpha[1];
        }

        // PV: repack P frags from acc_s (C-frag == A-frag layout), split hi/lo
        #pragma unroll
        for (int ks = 0; ks < 4; ks++) {
            uint32_t pa_h[4], pa_l[4];
            #pragma unroll
            for (int rr = 0; rr < 4; rr++) {
                const int nt = 2 * ks + (rr >> 1);
                const float p0 = acc_s[nt][(rr & 1) * 2 + 0];
                const float p1 = acc_s[nt][(rr & 1) * 2 + 1];
                const float h0 = __bfloat162float(__float2bfloat16(p0));
                const float h1 = __bfloat162float(__float2bfloat16(p1));
                pa_h[rr] = pack_bf16(h0, h1);
                pa_l[rr] = pack_bf16(p0 - h0, p1 - h1);
            }
            #pragma unroll
            for (int dp = 0; dp < 4; dp++) {
                uint32_t vh[4], vl[4];
                const uint32_t vo = (uint32_t)((ks * 16 + vr) * 72 + dp * 16 + vc) * 2;
                ldm_x4_trans(vh, sVh + vo);
                ldm_x4_trans(vl, sVl + vo);
                #pragma unroll
                for (int q = 0; q < 2; q++) {
                    const int nt = dp * 2 + q;
                    mma_bf16(acc_d[nt], pa_h, &vh[q * 2]);
                    mma_bf16(acc_d[nt], pa_h, &vl[q * 2]);
                    mma_bf16(acc_d[nt], pa_l, &vh[q * 2]);
                }
            }
        }
    }
    #undef PREFETCH

    const float inv0 = 1.f / l_run[0];
    const float inv1 = 1.f / l_run[1];
    #pragma unroll
    for (int nt = 0; nt < 8; nt++) {
        const int d = nt * 8 + 2 * (lane & 3);
        #pragma unroll
        for (int half = 0; half < 2; half++) {
            const int t_g = tc * 128 + wm + (lane >> 2) + half * 8;
            const float inv = half ? inv1 : inv0;
            float2 o;
            o.x = acc_d[nt][half * 2 + 0] * inv;
            o.y = acc_d[nt][half * 2 + 1] * inv;
            *(float2*)&g_ctx[((size_t)b_ * TT + t_g) * DM + h * DHH + d] = o;
        }
    }
}

// ---------------------------------------------------------------------------
extern "C" void kernel_launch(void* const* d_in, const int* in_sizes, int n_in,
                              void* d_out, int out_size)
{
    const float* x   = (const float*)d_in[0];
    const float* rel = (const float*)d_in[1];
    const float* Wq  = (const float*)d_in[2];
    const float* bq  = (const float*)d_in[3];
    const float* Wk  = (const float*)d_in[4];
    const float* bk  = (const float*)d_in[5];
    const float* Wv  = (const float*)d_in[6];
    const float* bv  = (const float*)d_in[7];
    const float* Wo  = (const float*)d_in[8];
    const float* bo  = (const float*)d_in[9];

    (void)in_sizes; (void)n_in; (void)out_size;

    cudaFuncSetAttribute(attn_tc, cudaFuncAttributeMaxDynamicSharedMemorySize, 147456);

    __nv_bfloat16 *pAhi, *pAlo, *pWhi, *pWlo;
    cudaGetSymbolAddress((void**)&pAhi, g_Ahi);
    cudaGetSymbolAddress((void**)&pAlo, g_Alo);
    cudaGetSymbolAddress((void**)&pWhi, g_Whi);
    cudaGetSymbolAddress((void**)&pWlo, g_Wlo);
    float* pctx;
    cudaGetSymbolAddress((void**)&pctx, g_ctx);

    convert_split<<<1024, 256>>>(x, pAhi, pAlo, BB*TT*DM);
    convert_split_w<<<dim3(64, 4), 256>>>(Wq, Wk, Wv, Wo, pWhi, pWlo);

    gemm_tc<0><<<dim3(32, 4, 3), 256>>>(pAhi, pAlo, pWhi, pWlo, bq, bk, bv, nullptr);

    pos_kernel<<<dim3(512, 8), 128>>>(rel);
    attn_tc<<<dim3(4, 8, 8), 256, 147456>>>();

    convert_split<<<1024, 256>>>(pctx, pAhi, pAlo, BB*TT*DM);
    gemm_tc<1><<<dim3(32, 4, 1), 256>>>(pAhi, pAlo, pWhi + 3*DM*DM, pWlo + 3*DM*DM,
                                        bo, nullptr, nullptr, (float*)d_out);
}

// round 6
// speedup vs baseline: 1.8943x; 1.0188x over previous
#include <cuda_runtime.h>
#include <cuda_bf16.h>
#include <math.h>
#include <stdint.h>

#define BB  8
#define TT  512
#define DM  512
#define NHH 8
#define DHH 64
#define LOG2E 1.4426950408889634f

// ---------------------------------------------------------------------------
// Scratch (static __device__ — no allocations allowed)
// ---------------------------------------------------------------------------
__device__ float g_Q[BB*NHH*TT*DHH];        // [B,NH,T,DH] fp32, scaled by log2e/8
__device__ float g_P[BB*NHH*TT*TT];         // position scores (log2 units)
__device__ float g_ctx[BB*TT*DM];           // attention context [B,T,D]
__device__ __nv_bfloat16 g_Ahi[BB*TT*DM];
__device__ __nv_bfloat16 g_Alo[BB*TT*DM];
__device__ __nv_bfloat16 g_Whi[4*DM*DM];
__device__ __nv_bfloat16 g_Wlo[4*DM*DM];
__device__ __nv_bfloat16 g_Qh[BB*NHH*TT*DHH], g_Ql[BB*NHH*TT*DHH];
__device__ __nv_bfloat16 g_Kh[BB*NHH*TT*DHH], g_Kl[BB*NHH*TT*DHH];
__device__ __nv_bfloat16 g_Vh[BB*NHH*TT*DHH], g_Vl[BB*NHH*TT*DHH];

// ---------------------------------------------------------------------------
// helpers
// ---------------------------------------------------------------------------
__device__ __forceinline__ uint32_t smem_u32(const void* p) {
    uint32_t a;
    asm("{ .reg .u64 t; cvta.to.shared.u64 t, %1; cvt.u32.u64 %0, t; }" : "=r"(a) : "l"(p));
    return a;
}
__device__ __forceinline__ void ldm_x4(uint32_t* r, uint32_t addr) {
    asm volatile("ldmatrix.sync.aligned.m8n8.x4.shared.b16 {%0,%1,%2,%3}, [%4];"
        : "=r"(r[0]), "=r"(r[1]), "=r"(r[2]), "=r"(r[3]) : "r"(addr));
}
__device__ __forceinline__ void ldm_x4_trans(uint32_t* r, uint32_t addr) {
    asm volatile("ldmatrix.sync.aligned.m8n8.x4.trans.shared.b16 {%0,%1,%2,%3}, [%4];"
        : "=r"(r[0]), "=r"(r[1]), "=r"(r[2]), "=r"(r[3]) : "r"(addr));
}
__device__ __forceinline__ void mma_bf16(float* d, const uint32_t* a, const uint32_t* b) {
    asm volatile("mma.sync.aligned.m16n8k16.row.col.f32.bf16.bf16.f32 "
        "{%0,%1,%2,%3}, {%4,%5,%6,%7}, {%8,%9}, {%0,%1,%2,%3};"
        : "+f"(d[0]), "+f"(d[1]), "+f"(d[2]), "+f"(d[3])
        : "r"(a[0]), "r"(a[1]), "r"(a[2]), "r"(a[3]), "r"(b[0]), "r"(b[1]));
}
__device__ __forceinline__ uint32_t pack_bf16(float lo, float hi) {
    __nv_bfloat162 t = __floats2bfloat162_rn(lo, hi);
    return *reinterpret_cast<uint32_t*>(&t);
}
__device__ __forceinline__ float ex2f(float x) {
    float r; asm("ex2.approx.ftz.f32 %0, %1;" : "=f"(r) : "f"(x)); return r;
}
#define CPASYNC16(daddr, sptr) \
    asm volatile("cp.async.cg.shared.global [%0], [%1], 16;" :: "r"(daddr), "l"(sptr) : "memory")
#define CPASYNC_COMMIT() asm volatile("cp.async.commit_group;" ::: "memory")
#define CPASYNC_WAIT1()  asm volatile("cp.async.wait_group 1;" ::: "memory")
#define CPASYNC_WAIT0()  asm volatile("cp.async.wait_group 0;" ::: "memory")

// ---------------------------------------------------------------------------
// fp32 -> bf16 (hi, lo) split conversion
// ---------------------------------------------------------------------------
__device__ __forceinline__ void split_store(const float* src, __nv_bfloat16* hi,
                                            __nv_bfloat16* lo, int i)
{
    float4 v = ((const float4*)src)[i];
    float f[4] = {v.x, v.y, v.z, v.w};
    unsigned short hb[4], lb[4];
    #pragma unroll
    for (int j = 0; j < 4; j++) {
        __nv_bfloat16 h = __float2bfloat16(f[j]);
        __nv_bfloat16 l = __float2bfloat16(f[j] - __bfloat162float(h));
        hb[j] = *reinterpret_cast<unsigned short*>(&h);
        lb[j] = *reinterpret_cast<unsigned short*>(&l);
    }
    ((ushort4*)hi)[i] = make_ushort4(hb[0], hb[1], hb[2], hb[3]);
    ((ushort4*)lo)[i] = make_ushort4(lb[0], lb[1], lb[2], lb[3]);
}

__global__ __launch_bounds__(256) void convert_split(
    const float* __restrict__ src, __nv_bfloat16* __restrict__ hi,
    __nv_bfloat16* __restrict__ lo, int n)
{
    const int n4 = n >> 2;
    for (int i = blockIdx.x * blockDim.x + threadIdx.x; i < n4; i += gridDim.x * blockDim.x)
        split_store(src, hi, lo, i);
}

__global__ __launch_bounds__(256) void convert_split_w(
    const float* __restrict__ w0, const float* __restrict__ w1,
    const float* __restrict__ w2, const float* __restrict__ w3,
    __nv_bfloat16* __restrict__ hi, __nv_bfloat16* __restrict__ lo)
{
    const int z = blockIdx.y;
    const float* src = (z == 0) ? w0 : (z == 1) ? w1 : (z == 2) ? w2 : w3;
    __nv_bfloat16* h = hi + (size_t)z * DM * DM;
    __nv_bfloat16* l = lo + (size_t)z * DM * DM;
    const int n4 = (DM * DM) >> 2;
    for (int i = blockIdx.x * blockDim.x + threadIdx.x; i < n4; i += gridDim.x * blockDim.x)
        split_store(src, h, l, i);
}

// ---------------------------------------------------------------------------
// mma.sync split-bf16 GEMM (unchanged)
// ---------------------------------------------------------------------------
template<int MODE>
__global__ __launch_bounds__(256) void gemm_tc(
    const __nv_bfloat16* __restrict__ Ahi, const __nv_bfloat16* __restrict__ Alo,
    const __nv_bfloat16* __restrict__ Whi, const __nv_bfloat16* __restrict__ Wlo,
    const float* __restrict__ bias0, const float* __restrict__ bias1,
    const float* __restrict__ bias2, float* __restrict__ out_override)
{
    __shared__ __align__(16) __nv_bfloat16 As[2][128][40];
    __shared__ __align__(16) __nv_bfloat16 Bs[2][128][40];

    const int tid  = threadIdx.x;
    const int wid  = tid >> 5;
    const int lane = tid & 31;
    const int m0 = blockIdx.x * 128;
    const int n0 = blockIdx.y * 128;
    const int z  = blockIdx.z;

    const float* bias; float scale;
    const __nv_bfloat16 *Wh, *Wl;
    __nv_bfloat16 *oh, *ol;
    if (MODE == 0) {
        bias  = (z == 0) ? bias0 : (z == 1) ? bias1 : bias2;
        scale = (z == 0) ? 0.125f * LOG2E : 1.0f;
        oh = (z == 0) ? g_Qh : (z == 1) ? g_Kh : g_Vh;
        ol = (z == 0) ? g_Ql : (z == 1) ? g_Kl : g_Vl;
        Wh = Whi + (size_t)z * DM * DM;
        Wl = Wlo + (size_t)z * DM * DM;
    } else {
        bias = bias0; scale = 1.0f;
        Wh = Whi; Wl = Wlo; oh = nullptr; ol = nullptr;
    }

    const int grow = tid >> 1;
    const int gcol = (tid & 1) * 16;
    const __nv_bfloat16* gA = Ahi + (size_t)(m0 + grow) * DM + gcol;
    const __nv_bfloat16* gAl= Alo + (size_t)(m0 + grow) * DM + gcol;
    const __nv_bfloat16* gB = Wh  + (size_t)(n0 + grow) * DM + gcol;
    const __nv_bfloat16* gBl= Wl  + (size_t)(n0 + grow) * DM + gcol;

    uint4 pAh[2], pAl[2], pBh[2], pBl[2];
    #define LOAD_REGS(kc) do { \
        const int off = (kc) * 32; \
        pAh[0] = *(const uint4*)(gA  + off); pAh[1] = *(const uint4*)(gA  + off + 8); \
        pAl[0] = *(const uint4*)(gAl + off); pAl[1] = *(const uint4*)(gAl + off + 8); \
        pBh[0] = *(const uint4*)(gB  + off); pBh[1] = *(const uint4*)(gB  + off + 8); \
        pBl[0] = *(const uint4*)(gBl + off); pBl[1] = *(const uint4*)(gBl + off + 8); \
    } while (0)

    float acc[4][4][4];
    #pragma unroll
    for (int i = 0; i < 4; i++)
        #pragma unroll
        for (int j = 0; j < 4; j++)
            #pragma unroll
            for (int v = 0; v < 4; v++) acc[i][j][v] = 0.f;

    const int wm = (wid >> 2) * 64;
    const int wn = (wid & 3) * 32;
    const int ar = (lane & 7) + ((lane >> 3) & 1) * 8;
    const int ak = ((lane >> 4) & 1) * 8;
    const int br = (lane & 7) + ((lane >> 4) & 1) * 8;
    const int bk = ((lane >> 3) & 1) * 8;

    const uint32_t aBase = smem_u32(&As[0][0][0]);
    const uint32_t bBase = smem_u32(&Bs[0][0][0]);
    const uint32_t bufStride = 128 * 40 * 2;

    LOAD_REGS(0);

    for (int kc = 0; kc < 16; kc++) {
        __syncthreads();
        *(uint4*)&As[0][grow][gcol]     = pAh[0];
        *(uint4*)&As[0][grow][gcol + 8] = pAh[1];
        *(uint4*)&As[1][grow][gcol]     = pAl[0];
        *(uint4*)&As[1][grow][gcol + 8] = pAl[1];
        *(uint4*)&Bs[0][grow][gcol]     = pBh[0];
        *(uint4*)&Bs[0][grow][gcol + 8] = pBh[1];
        *(uint4*)&Bs[1][grow][gcol]     = pBl[0];
        *(uint4*)&Bs[1][grow][gcol + 8] = pBl[1];
        __syncthreads();

        if (kc < 15) LOAD_REGS(kc + 1);

        #pragma unroll
        for (int ks = 0; ks < 2; ks++) {
            uint32_t ah[4][4], al[4][4];
            #pragma unroll
            for (int mt = 0; mt < 4; mt++) {
                const uint32_t ao = (uint32_t)((wm + mt * 16 + ar) * 40 + ks * 16 + ak) * 2;
                ldm_x4(ah[mt], aBase + ao);
                ldm_x4(al[mt], aBase + bufStride + ao);
            }
            uint32_t bh[2][4], bl[2][4];
            #pragma unroll
            for (int p = 0; p < 2; p++) {
                const uint32_t bo = (uint32_t)((wn + p * 16 + br) * 40 + ks * 16 + bk) * 2;
                ldm_x4(bh[p], bBase + bo);
                ldm_x4(bl[p], bBase + bufStride + bo);
            }
            #pragma unroll
            for (int mt = 0; mt < 4; mt++)
                #pragma unroll
                for (int nt = 0; nt < 4; nt++) {
                    const int p = nt >> 1, o = (nt & 1) * 2;
                    mma_bf16(acc[mt][nt], ah[mt], &bh[p][o]);
                    mma_bf16(acc[mt][nt], ah[mt], &bl[p][o]);
                    mma_bf16(acc[mt][nt], al[mt], &bh[p][o]);
                }
        }
    }
    #undef LOAD_REGS

    #pragma unroll
    for (int mt = 0; mt < 4; mt++) {
        #pragma unroll
        for (int nt = 0; nt < 4; nt++) {
            const int col = n0 + wn + nt * 8 + 2 * (lane & 3);
            const float bx = bias[col], by = bias[col + 1];
            #pragma unroll
            for (int half = 0; half < 2; half++) {
                const int m = m0 + wm + mt * 16 + (lane >> 2) + half * 8;
                float ox = (acc[mt][nt][half * 2 + 0] + bx) * scale;
                float oy = (acc[mt][nt][half * 2 + 1] + by) * scale;
                if (MODE == 0) {
                    const int b_ = m >> 9, t = m & 511, h = col >> 6, d = col & 63;
                    const size_t idx = (((size_t)b_ * NHH + h) * TT + t) * DHH + d;
                    __nv_bfloat16 hx = __float2bfloat16(ox);
                    __nv_bfloat16 hy = __float2bfloat16(oy);
                    __nv_bfloat16 lx = __float2bfloat16(ox - __bfloat162float(hx));
                    __nv_bfloat16 ly = __float2bfloat16(oy - __bfloat162float(hy));
                    *(__nv_bfloat162*)&oh[idx] = __nv_bfloat162(hx, hy);
                    *(__nv_bfloat162*)&ol[idx] = __nv_bfloat162(lx, ly);
                    if (z == 0) *(float2*)&g_Q[idx] = make_float2(ox, oy);
                } else {
                    *(float2*)&out_override[(size_t)m * DM + col] = make_float2(ox, oy);
                }
            }
        }
    }
}

// ---------------------------------------------------------------------------
// Position kernel (tensor cores): P[b,h,t,s] = Q[b,h,t,:] . rel[t,s,h*64:...]
// CTA = (t,h), 128 threads. Per 64-s chunk: LDG fp32 rel -> split bf16 hi/lo
// -> STS into double-buffered [64][72] tiles -> 3-term split MMA with
// A = Q[8x64] (rows 8..15 zero) prebuilt in registers. P written fp32.
// ---------------------------------------------------------------------------
__global__ __launch_bounds__(128) void pos_tc(const float* __restrict__ rel)
{
    __shared__ __align__(16) __nv_bfloat16 Rh[2][64][72];
    __shared__ __align__(16) __nv_bfloat16 Rl[2][64][72];

    const int t = blockIdx.x;
    const int h = blockIdx.y;
    const int tid  = threadIdx.x;
    const int wid  = tid >> 5;
    const int lane = tid & 31;

    // --- Build A fragments from fp32 Q (log2e-scaled): rows = batch 0..7 ---
    // m16n8k16 A frag: a0 = T[l/4][(l%4)*2 +0,1], a2 = T[l/4][(l%4)*2+8 +0,1],
    // a1 = a3 = rows 8..15 -> zero.
    uint32_t qa_h[4][2], qa_l[4][2];   // [ks][{a0,a2}]
    {
        const int b_ = lane >> 2;
        const int kk = (lane & 3) * 2;
        const float* qrow = &g_Q[(((size_t)b_ * NHH + h) * TT + t) * DHH];
        #pragma unroll
        for (int ks = 0; ks < 4; ks++) {
            float2 f0 = *(const float2*)&qrow[ks * 16 + kk];
            float2 f1 = *(const float2*)&qrow[ks * 16 + kk + 8];
            float h00 = __bfloat162float(__float2bfloat16(f0.x));
            float h01 = __bfloat162float(__float2bfloat16(f0.y));
            float h10 = __bfloat162float(__float2bfloat16(f1.x));
            float h11 = __bfloat162float(__float2bfloat16(f1.y));
            qa_h[ks][0] = pack_bf16(h00, h01);
            qa_h[ks][1] = pack_bf16(h10, h11);
            qa_l[ks][0] = pack_bf16(f0.x - h00, f0.y - h01);
            qa_l[ks][1] = pack_bf16(f1.x - h10, f1.y - h11);
        }
    }

    // rel chunk loader: thread covers row r = tid>>1, d-half dh = tid&1 (32 f)
    const int r  = tid >> 1;
    const int dh = (tid & 1) * 32;
    const float4* gsrc = (const float4*)(rel + ((size_t)t * TT) * DM + (size_t)r * DM + h * DHH + dh);
    const size_t chunk_stride4 = (size_t)64 * DM / 4;   // 64 s rows in float4 units

    float4 rv[8];
    #pragma unroll
    for (int j = 0; j < 8; j++) rv[j] = gsrc[j];        // chunk 0

    // B-frag ldmatrix offsets (same pattern as attn K)
    const int br = (lane & 7) + ((lane >> 4) & 1) * 8;
    const int bk = ((lane >> 3) & 1) * 8;
    const uint32_t sRh = smem_u32(&Rh[0][0][0]);
    const uint32_t sRl = smem_u32(&Rl[0][0][0]);
    const uint32_t bufB = 64 * 72 * 2;                  // bytes per buffer

    float* Pout = &g_P[(((size_t)(lane >> 2) * NHH + h) * TT + t) * TT];
    const int scol0 = wid * 16 + (lane & 3) * 2;        // warp's s base within chunk

    for (int c = 0; c < 8; c++) {
        const int buf = c & 1;
        // STS current chunk (split hi/lo)
        #pragma unroll
        for (int j = 0; j < 8; j += 2) {
            float f[8] = {rv[j].x, rv[j].y, rv[j].z, rv[j].w,
                          rv[j+1].x, rv[j+1].y, rv[j+1].z, rv[j+1].w};
            uint32_t ph[4], pl[4];
            #pragma unroll
            for (int q = 0; q < 4; q++) {
                float h0 = __bfloat162float(__float2bfloat16(f[q*2]));
                float h1 = __bfloat162float(__float2bfloat16(f[q*2+1]));
                ph[q] = pack_bf16(h0, h1);
                pl[q] = pack_bf16(f[q*2] - h0, f[q*2+1] - h1);
            }
            *(uint4*)&Rh[buf][r][dh + j * 4] = make_uint4(ph[0], ph[1], ph[2], ph[3]);
            *(uint4*)&Rl[buf][r][dh + j * 4] = make_uint4(pl[0], pl[1], pl[2], pl[3]);
        }
        __syncthreads();

        // issue next chunk's loads before MMA
        if (c < 7) {
            const float4* gs = gsrc + (size_t)(c + 1) * chunk_stride4;
            #pragma unroll
            for (int j = 0; j < 8; j++) rv[j] = gs[j];
        }

        // MMA: warp w handles s in [w*16, w*16+16) of this chunk = 2 n-tiles
        float acc[2][4];
        #pragma unroll
        for (int nt = 0; nt < 2; nt++)
            #pragma unroll
            for (int v = 0; v < 4; v++) acc[nt][v] = 0.f;

        #pragma unroll
        for (int ks = 0; ks < 4; ks++) {
            uint32_t bh[4], bl[4];
            const uint32_t bo = (uint32_t)buf * bufB +
                                (uint32_t)((wid * 16 + br) * 72 + ks * 16 + bk) * 2;
            ldm_x4(bh, sRh + bo);
            ldm_x4(bl, sRl + bo);
            uint32_t a_h[4] = {qa_h[ks][0], 0u, qa_h[ks][1], 0u};
            uint32_t a_l[4] = {qa_l[ks][0], 0u, qa_l[ks][1], 0u};
            #pragma unroll
            for (int q = 0; q < 2; q++) {
                mma_bf16(acc[q], a_h, &bh[q * 2]);
                mma_bf16(acc[q], a_h, &bl[q * 2]);
                mma_bf16(acc[q], a_l, &bh[q * 2]);
            }
        }

        // write P rows 0..7 (c0,c1 = batch row lane>>2)
        #pragma unroll
        for (int q = 0; q < 2; q++) {
            const int s = c * 64 + scol0 + q * 8;
            *(float2*)&Pout[s] = make_float2(acc[q][0], acc[q][1]);
        }
        __syncthreads();   // protect buf reuse (2 buffers, one-chunk skew)
    }
}

// ---------------------------------------------------------------------------
// Tensor-core flash attention with 3-stage cp.async K/V pipeline (unchanged)
// ---------------------------------------------------------------------------
__global__ __launch_bounds__(256) void attn_tc()
{
    extern __shared__ __nv_bfloat16 smb[];
    __nv_bfloat16* Qh = smb;
    __nv_bfloat16* Ql = Qh + 128*72;

    const int tc = blockIdx.x, h = blockIdx.y, b_ = blockIdx.z;
    const int tid  = threadIdx.x;
    const int wid  = tid >> 5;
    const int lane = tid & 31;

    const size_t headoff = ((size_t)b_ * NHH + h) * TT * DHH;
    const __nv_bfloat16* gQh = g_Qh + headoff + (size_t)tc * 128 * DHH;
    const __nv_bfloat16* gQl = g_Ql + headoff + (size_t)tc * 128 * DHH;
    const __nv_bfloat16* gKh = g_Kh + headoff;
    const __nv_bfloat16* gKl = g_Kl + headoff;
    const __nv_bfloat16* gVh = g_Vh + headoff;
    const __nv_bfloat16* gVl = g_Vl + headoff;
    const float* Pg = g_P + (((size_t)b_ * NHH + h) * TT + tc * 128) * TT;

    const uint32_t sbase = smem_u32(smb);

    #pragma unroll
    for (int it = 0; it < 4; it++) {
        const int idx = it * 256 + tid;
        const int r = idx >> 3, c = (idx & 7) * 8;
        *(uint4*)&Qh[r * 72 + c] = *(const uint4*)&gQh[r * 64 + c];
        *(uint4*)&Ql[r * 72 + c] = *(const uint4*)&gQl[r * 64 + c];
    }

    #define PREFETCH(sc_, st_) do { \
        const uint32_t so = sbase + 36864u + (uint32_t)(st_) * 36864u; \
        _Pragma("unroll") \
        for (int it = 0; it < 2; it++) { \
            const int idx = it * 256 + tid; \
            const int r = idx >> 3, c = (idx & 7) * 8; \
            const uint32_t d = (uint32_t)(r * 72 + c) * 2; \
            const size_t g = (size_t)((sc_) * 64 + r) * 64 + c; \
            CPASYNC16(so + d,          gKh + g); \
            CPASYNC16(so +  9216u + d, gKl + g); \
            CPASYNC16(so + 18432u + d, gVh + g); \
            CPASYNC16(so + 27648u + d, gVl + g); \
        } \
        CPASYNC_COMMIT(); \
    } while (0)

    const int wm = wid * 16;
    const int ar = (lane & 7) + ((lane >> 3) & 1) * 8;
    const int ak = ((lane >> 4) & 1) * 8;
    const int br = (lane & 7) + ((lane >> 4) & 1) * 8;
    const int bk = ((lane >> 3) & 1) * 8;
    const int vr = lane & 15;
    const int vc = ((lane >> 4) & 1) * 8;

    const uint32_t sQh = sbase, sQl = sbase + 18432u;

    float acc_d[8][4];
    #pragma unroll
    for (int nt = 0; nt < 8; nt++)
        #pragma unroll
        for (int v = 0; v < 4; v++) acc_d[nt][v] = 0.f;
    float m_run[2] = {-INFINITY, -INFINITY};
    float l_run[2] = {0.f, 0.f};

    PREFETCH(0, 0);

    for (int sc = 0; sc < 8; sc++) {
        const int st = sc % 3;
        if (sc < 7) { PREFETCH(sc + 1, (sc + 1) % 3); CPASYNC_WAIT1(); }
        else        { CPASYNC_WAIT0(); }
        __syncthreads();

        const uint32_t sKh = sbase + 36864u + (uint32_t)st * 36864u;
        const uint32_t sKl = sKh +  9216u;
        const uint32_t sVh = sKh + 18432u;
        const uint32_t sVl = sKh + 27648u;

        float acc_s[8][4];
        #pragma unroll
        for (int nt = 0; nt < 8; nt++) {
            const int scol = sc * 64 + nt * 8 + 2 * (lane & 3);
            #pragma unroll
            for (int half = 0; half < 2; half++) {
                const int trow = wm + (lane >> 2) + half * 8;
                float2 pv = *(const float2*)&Pg[(size_t)trow * TT + scol];
                acc_s[nt][half * 2 + 0] = pv.x;
                acc_s[nt][half * 2 + 1] = pv.y;
            }
        }

        #pragma unroll
        for (int ks = 0; ks < 4; ks++) {
            uint32_t ah[4], al[4];
            const uint32_t ao = (uint32_t)((wm + ar) * 72 + ks * 16 + ak) * 2;
            ldm_x4(ah, sQh + ao);
            ldm_x4(al, sQl + ao);
            #pragma unroll
            for (int p = 0; p < 4; p++) {
                uint32_t bh[4], bl[4];
                const uint32_t bo = (uint32_t)((p * 16 + br) * 72 + ks * 16 + bk) * 2;
                ldm_x4(bh, sKh + bo);
                ldm_x4(bl, sKl + bo);
                #pragma unroll
                for (int q = 0; q < 2; q++) {
                    const int nt = p * 2 + q;
                    mma_bf16(acc_s[nt], ah, &bh[q * 2]);
                    mma_bf16(acc_s[nt], ah, &bl[q * 2]);
                    mma_bf16(acc_s[nt], al, &bh[q * 2]);
                }
            }
        }

        float alpha[2];
        #pragma unroll
        for (int half = 0; half < 2; half++) {
            float mx = m_run[half];
            #pragma unroll
            for (int nt = 0; nt < 8; nt++)
                mx = fmaxf(mx, fmaxf(acc_s[nt][half*2], acc_s[nt][half*2+1]));
            mx = fmaxf(mx, __shfl_xor_sync(0xffffffffu, mx, 1));
            mx = fmaxf(mx, __shfl_xor_sync(0xffffffffu, mx, 2));
            alpha[half] = ex2f(m_run[half] - mx);
            float sum = 0.f;
            #pragma unroll
            for (int nt = 0; nt < 8; nt++) {
                float p0 = ex2f(acc_s[nt][half*2]   - mx);
                float p1 = ex2f(acc_s[nt][half*2+1] - mx);
                acc_s[nt][half*2]   = p0;
                acc_s[nt][half*2+1] = p1;
                sum += p0 + p1;
            }
            sum += __shfl_xor_sync(0xffffffffu, sum, 1);
            sum += __shfl_xor_sync(0xffffffffu, sum, 2);
            m_run[half] = mx;
            l_run[half] = l_run[half] * alpha[half] + sum;
        }
        #pragma unroll
        for (int nt = 0; nt < 8; nt++) {
            acc_d[nt][0] *= alpha[0]; acc_d[nt][1] *= alpha[0];
            acc_d[nt][2] *= alpha[1]; acc_d[nt][3] *= alpha[1];
        }

        #pragma unroll
        for (int ks = 0; ks < 4; ks++) {
            uint32_t pa_h[4], pa_l[4];
            #pragma unroll
            for (int rr = 0; rr < 4; rr++) {
                const int nt = 2 * ks + (rr >> 1);
                const float p0 = acc_s[nt][(rr & 1) * 2 + 0];
                const float p1 = acc_s[nt][(rr & 1) * 2 + 1];
                const float h0 = __bfloat162float(__float2bfloat16(p0));
                const float h1 = __bfloat162float(__float2bfloat16(p1));
                pa_h[rr] = pack_bf16(h0, h1);
                pa_l[rr] = pack_bf16(p0 - h0, p1 - h1);
            }
            #pragma unroll
            for (int dp = 0; dp < 4; dp++) {
                uint32_t vh[4], vl[4];
                const uint32_t vo = (uint32_t)((ks * 16 + vr) * 72 + dp * 16 + vc) * 2;
                ldm_x4_trans(vh, sVh + vo);
                ldm_x4_trans(vl, sVl + vo);
                #pragma unroll
                for (int q = 0; q < 2; q++) {
                    const int nt = dp * 2 + q;
                    mma_bf16(acc_d[nt], pa_h, &vh[q * 2]);
                    mma_bf16(acc_d[nt], pa_h, &vl[q * 2]);
                    mma_bf16(acc_d[nt], pa_l, &vh[q * 2]);
                }
            }
        }
    }
    #undef PREFETCH

    const float inv0 = 1.f / l_run[0];
    const float inv1 = 1.f / l_run[1];
    #pragma unroll
    for (int nt = 0; nt < 8; nt++) {
        const int d = nt * 8 + 2 * (lane & 3);
        #pragma unroll
        for (int half = 0; half < 2; half++) {
            const int t_g = tc * 128 + wm + (lane >> 2) + half * 8;
            const float inv = half ? inv1 : inv0;
            float2 o;
            o.x = acc_d[nt][half * 2 + 0] * inv;
            o.y = acc_d[nt][half * 2 + 1] * inv;
            *(float2*)&g_ctx[((size_t)b_ * TT + t_g) * DM + h * DHH + d] = o;
        }
    }
}

// ---------------------------------------------------------------------------
extern "C" void kernel_launch(void* const* d_in, const int* in_sizes, int n_in,
                              void* d_out, int out_size)
{
    const float* x   = (const float*)d_in[0];
    const float* rel = (const float*)d_in[1];
    const float* Wq  = (const float*)d_in[2];
    const float* bq  = (const float*)d_in[3];
    const float* Wk  = (const float*)d_in[4];
    const float* bk  = (const float*)d_in[5];
    const float* Wv  = (const float*)d_in[6];
    const float* bv  = (const float*)d_in[7];
    const float* Wo  = (const float*)d_in[8];
    const float* bo  = (const float*)d_in[9];

    (void)in_sizes; (void)n_in; (void)out_size;

    cudaFuncSetAttribute(attn_tc, cudaFuncAttributeMaxDynamicSharedMemorySize, 147456);

    __nv_bfloat16 *pAhi, *pAlo, *pWhi, *pWlo;
    cudaGetSymbolAddress((void**)&pAhi, g_Ahi);
    cudaGetSymbolAddress((void**)&pAlo, g_Alo);
    cudaGetSymbolAddress((void**)&pWhi, g_Whi);
    cudaGetSymbolAddress((void**)&pWlo, g_Wlo);
    float* pctx;
    cudaGetSymbolAddress((void**)&pctx, g_ctx);

    convert_split<<<1024, 256>>>(x, pAhi, pAlo, BB*TT*DM);
    convert_split_w<<<dim3(64, 4), 256>>>(Wq, Wk, Wv, Wo, pWhi, pWlo);

    gemm_tc<0><<<dim3(32, 4, 3), 256>>>(pAhi, pAlo, pWhi, pWlo, bq, bk, bv, nullptr);

    pos_tc<<<dim3(512, 8), 128>>>(rel);
    attn_tc<<<dim3(4, 8, 8), 256, 147456>>>();

    convert_split<<<1024, 256>>>(pctx, pAhi, pAlo, BB*TT*DM);
    gemm_tc<1><<<dim3(32, 4, 1), 256>>>(pAhi, pAlo, pWhi + 3*DM*DM, pWlo + 3*DM*DM,
                                        bo, nullptr, nullptr, (float*)d_out);
}

// round 8
// speedup vs baseline: 2.3549x; 1.2432x over previous
#include <cuda_runtime.h>
#include <cuda_bf16.h>
#include <math.h>
#include <stdint.h>

#define BB  8
#define TT  512
#define DM  512
#define NHH 8
#define DHH 64
#define LOG2E 1.4426950408889634f

// ---------------------------------------------------------------------------
// Scratch (static __device__ — no allocations allowed)
// ---------------------------------------------------------------------------
__device__ float g_Q[BB*NHH*TT*DHH];        // [B,NH,T,DH] fp32, scaled by log2e/8
__device__ float g_P[BB*NHH*TT*TT];         // position scores (log2 units)
__device__ float g_ctx[BB*TT*DM];           // attention context [B,T,D]
__device__ __nv_bfloat16 g_Ahi[BB*TT*DM];
__device__ __nv_bfloat16 g_Alo[BB*TT*DM];
__device__ __nv_bfloat16 g_Whi[4*DM*DM];
__device__ __nv_bfloat16 g_Wlo[4*DM*DM];
__device__ __nv_bfloat16 g_Qh[BB*NHH*TT*DHH], g_Ql[BB*NHH*TT*DHH];
__device__ __nv_bfloat16 g_Kh[BB*NHH*TT*DHH], g_Kl[BB*NHH*TT*DHH];
__device__ __nv_bfloat16 g_Vh[BB*NHH*TT*DHH], g_Vl[BB*NHH*TT*DHH];

// ---------------------------------------------------------------------------
// helpers
// ---------------------------------------------------------------------------
__device__ __forceinline__ uint32_t smem_u32(const void* p) {
    uint32_t a;
    asm("{ .reg .u64 t; cvta.to.shared.u64 t, %1; cvt.u32.u64 %0, t; }" : "=r"(a) : "l"(p));
    return a;
}
__device__ __forceinline__ void ldm_x4(uint32_t* r, uint32_t addr) {
    asm volatile("ldmatrix.sync.aligned.m8n8.x4.shared.b16 {%0,%1,%2,%3}, [%4];"
        : "=r"(r[0]), "=r"(r[1]), "=r"(r[2]), "=r"(r[3]) : "r"(addr));
}
__device__ __forceinline__ void ldm_x4_trans(uint32_t* r, uint32_t addr) {
    asm volatile("ldmatrix.sync.aligned.m8n8.x4.trans.shared.b16 {%0,%1,%2,%3}, [%4];"
        : "=r"(r[0]), "=r"(r[1]), "=r"(r[2]), "=r"(r[3]) : "r"(addr));
}
__device__ __forceinline__ void mma_bf16(float* d, const uint32_t* a, const uint32_t* b) {
    asm volatile("mma.sync.aligned.m16n8k16.row.col.f32.bf16.bf16.f32 "
        "{%0,%1,%2,%3}, {%4,%5,%6,%7}, {%8,%9}, {%0,%1,%2,%3};"
        : "+f"(d[0]), "+f"(d[1]), "+f"(d[2]), "+f"(d[3])
        : "r"(a[0]), "r"(a[1]), "r"(a[2]), "r"(a[3]), "r"(b[0]), "r"(b[1]));
}
__device__ __forceinline__ uint32_t pack_bf16(float lo, float hi) {
    __nv_bfloat162 t = __floats2bfloat162_rn(lo, hi);
    return *reinterpret_cast<uint32_t*>(&t);
}
__device__ __forceinline__ float ex2f(float x) {
    float r; asm("ex2.approx.ftz.f32 %0, %1;" : "=f"(r) : "f"(x)); return r;
}
#define CPASYNC16(daddr, sptr) \
    asm volatile("cp.async.cg.shared.global [%0], [%1], 16;" :: "r"(daddr), "l"(sptr) : "memory")
#define CPASYNC_COMMIT() asm volatile("cp.async.commit_group;" ::: "memory")
#define CPASYNC_WAIT2()  asm volatile("cp.async.wait_group 2;" ::: "memory")
#define CPASYNC_WAIT1()  asm volatile("cp.async.wait_group 1;" ::: "memory")
#define CPASYNC_WAIT0()  asm volatile("cp.async.wait_group 0;" ::: "memory")

// ---------------------------------------------------------------------------
// fp32 -> bf16 (hi, lo) split conversion
// ---------------------------------------------------------------------------
__device__ __forceinline__ void split_store(const float* src, __nv_bfloat16* hi,
                                            __nv_bfloat16* lo, int i)
{
    float4 v = ((const float4*)src)[i];
    float f[4] = {v.x, v.y, v.z, v.w};
    unsigned short hb[4], lb[4];
    #pragma unroll
    for (int j = 0; j < 4; j++) {
        __nv_bfloat16 h = __float2bfloat16(f[j]);
        __nv_bfloat16 l = __float2bfloat16(f[j] - __bfloat162float(h));
        hb[j] = *reinterpret_cast<unsigned short*>(&h);
        lb[j] = *reinterpret_cast<unsigned short*>(&l);
    }
    ((ushort4*)hi)[i] = make_ushort4(hb[0], hb[1], hb[2], hb[3]);
    ((ushort4*)lo)[i] = make_ushort4(lb[0], lb[1], lb[2], lb[3]);
}

__global__ __launch_bounds__(256) void convert_split(
    const float* __restrict__ src, __nv_bfloat16* __restrict__ hi,
    __nv_bfloat16* __restrict__ lo, int n)
{
    const int n4 = n >> 2;
    for (int i = blockIdx.x * blockDim.x + threadIdx.x; i < n4; i += gridDim.x * blockDim.x)
        split_store(src, hi, lo, i);
}

__global__ __launch_bounds__(256) void convert_split_w(
    const float* __restrict__ w0, const float* __restrict__ w1,
    const float* __restrict__ w2, const float* __restrict__ w3,
    __nv_bfloat16* __restrict__ hi, __nv_bfloat16* __restrict__ lo)
{
    const int z = blockIdx.y;
    const float* src = (z == 0) ? w0 : (z == 1) ? w1 : (z == 2) ? w2 : w3;
    __nv_bfloat16* h = hi + (size_t)z * DM * DM;
    __nv_bfloat16* l = lo + (size_t)z * DM * DM;
    const int n4 = (DM * DM) >> 2;
    for (int i = blockIdx.x * blockDim.x + threadIdx.x; i < n4; i += gridDim.x * blockDim.x)
        split_store(src, h, l, i);
}

// ---------------------------------------------------------------------------
// mma.sync split-bf16 GEMM (unchanged)
// ---------------------------------------------------------------------------
template<int MODE>
__global__ __launch_bounds__(256) void gemm_tc(
    const __nv_bfloat16* __restrict__ Ahi, const __nv_bfloat16* __restrict__ Alo,
    const __nv_bfloat16* __restrict__ Whi, const __nv_bfloat16* __restrict__ Wlo,
    const float* __restrict__ bias0, const float* __restrict__ bias1,
    const float* __restrict__ bias2, float* __restrict__ out_override)
{
    __shared__ __align__(16) __nv_bfloat16 As[2][128][40];
    __shared__ __align__(16) __nv_bfloat16 Bs[2][128][40];

    const int tid  = threadIdx.x;
    const int wid  = tid >> 5;
    const int lane = tid & 31;
    const int m0 = blockIdx.x * 128;
    const int n0 = blockIdx.y * 128;
    const int z  = blockIdx.z;

    const float* bias; float scale;
    const __nv_bfloat16 *Wh, *Wl;
    __nv_bfloat16 *oh, *ol;
    if (MODE == 0) {
        bias  = (z == 0) ? bias0 : (z == 1) ? bias1 : bias2;
        scale = (z == 0) ? 0.125f * LOG2E : 1.0f;
        oh = (z == 0) ? g_Qh : (z == 1) ? g_Kh : g_Vh;
        ol = (z == 0) ? g_Ql : (z == 1) ? g_Kl : g_Vl;
        Wh = Whi + (size_t)z * DM * DM;
        Wl = Wlo + (size_t)z * DM * DM;
    } else {
        bias = bias0; scale = 1.0f;
        Wh = Whi; Wl = Wlo; oh = nullptr; ol = nullptr;
    }

    const int grow = tid >> 1;
    const int gcol = (tid & 1) * 16;
    const __nv_bfloat16* gA = Ahi + (size_t)(m0 + grow) * DM + gcol;
    const __nv_bfloat16* gAl= Alo + (size_t)(m0 + grow) * DM + gcol;
    const __nv_bfloat16* gB = Wh  + (size_t)(n0 + grow) * DM + gcol;
    const __nv_bfloat16* gBl= Wl  + (size_t)(n0 + grow) * DM + gcol;

    uint4 pAh[2], pAl[2], pBh[2], pBl[2];
    #define LOAD_REGS(kc) do { \
        const int off = (kc) * 32; \
        pAh[0] = *(const uint4*)(gA  + off); pAh[1] = *(const uint4*)(gA  + off + 8); \
        pAl[0] = *(const uint4*)(gAl + off); pAl[1] = *(const uint4*)(gAl + off + 8); \
        pBh[0] = *(const uint4*)(gB  + off); pBh[1] = *(const uint4*)(gB  + off + 8); \
        pBl[0] = *(const uint4*)(gBl + off); pBl[1] = *(const uint4*)(gBl + off + 8); \
    } while (0)

    float acc[4][4][4];
    #pragma unroll
    for (int i = 0; i < 4; i++)
        #pragma unroll
        for (int j = 0; j < 4; j++)
            #pragma unroll
            for (int v = 0; v < 4; v++) acc[i][j][v] = 0.f;

    const int wm = (wid >> 2) * 64;
    const int wn = (wid & 3) * 32;
    const int ar = (lane & 7) + ((lane >> 3) & 1) * 8;
    const int ak = ((lane >> 4) & 1) * 8;
    const int br = (lane & 7) + ((lane >> 4) & 1) * 8;
    const int bk = ((lane >> 3) & 1) * 8;

    const uint32_t aBase = smem_u32(&As[0][0][0]);
    const uint32_t bBase = smem_u32(&Bs[0][0][0]);
    const uint32_t bufStride = 128 * 40 * 2;

    LOAD_REGS(0);

    for (int kc = 0; kc < 16; kc++) {
        __syncthreads();
        *(uint4*)&As[0][grow][gcol]     = pAh[0];
        *(uint4*)&As[0][grow][gcol + 8] = pAh[1];
        *(uint4*)&As[1][grow][gcol]     = pAl[0];
        *(uint4*)&As[1][grow][gcol + 8] = pAl[1];
        *(uint4*)&Bs[0][grow][gcol]     = pBh[0];
        *(uint4*)&Bs[0][grow][gcol + 8] = pBh[1];
        *(uint4*)&Bs[1][grow][gcol]     = pBl[0];
        *(uint4*)&Bs[1][grow][gcol + 8] = pBl[1];
        __syncthreads();

        if (kc < 15) LOAD_REGS(kc + 1);

        #pragma unroll
        for (int ks = 0; ks < 2; ks++) {
            uint32_t ah[4][4], al[4][4];
            #pragma unroll
            for (int mt = 0; mt < 4; mt++) {
                const uint32_t ao = (uint32_t)((wm + mt * 16 + ar) * 40 + ks * 16 + ak) * 2;
                ldm_x4(ah[mt], aBase + ao);
                ldm_x4(al[mt], aBase + bufStride + ao);
            }
            uint32_t bh[2][4], bl[2][4];
            #pragma unroll
            for (int p = 0; p < 2; p++) {
                const uint32_t bo = (uint32_t)((wn + p * 16 + br) * 40 + ks * 16 + bk) * 2;
                ldm_x4(bh[p], bBase + bo);
                ldm_x4(bl[p], bBase + bufStride + bo);
            }
            #pragma unroll
            for (int mt = 0; mt < 4; mt++)
                #pragma unroll
                for (int nt = 0; nt < 4; nt++) {
                    const int p = nt >> 1, o = (nt & 1) * 2;
                    mma_bf16(acc[mt][nt], ah[mt], &bh[p][o]);
                    mma_bf16(acc[mt][nt], ah[mt], &bl[p][o]);
                    mma_bf16(acc[mt][nt], al[mt], &bh[p][o]);
                }
        }
    }
    #undef LOAD_REGS

    #pragma unroll
    for (int mt = 0; mt < 4; mt++) {
        #pragma unroll
        for (int nt = 0; nt < 4; nt++) {
            const int col = n0 + wn + nt * 8 + 2 * (lane & 3);
            const float bx = bias[col], by = bias[col + 1];
            #pragma unroll
            for (int half = 0; half < 2; half++) {
                const int m = m0 + wm + mt * 16 + (lane >> 2) + half * 8;
                float ox = (acc[mt][nt][half * 2 + 0] + bx) * scale;
                float oy = (acc[mt][nt][half * 2 + 1] + by) * scale;
                if (MODE == 0) {
                    const int b_ = m >> 9, t = m & 511, h = col >> 6, d = col & 63;
                    const size_t idx = (((size_t)b_ * NHH + h) * TT + t) * DHH + d;
                    __nv_bfloat16 hx = __float2bfloat16(ox);
                    __nv_bfloat16 hy = __float2bfloat16(oy);
                    __nv_bfloat16 lx = __float2bfloat16(ox - __bfloat162float(hx));
                    __nv_bfloat16 ly = __float2bfloat16(oy - __bfloat162float(hy));
                    *(__nv_bfloat162*)&oh[idx] = __nv_bfloat162(hx, hy);
                    *(__nv_bfloat162*)&ol[idx] = __nv_bfloat162(lx, ly);
                    if (z == 0) *(float2*)&g_Q[idx] = make_float2(ox, oy);
                } else {
                    *(float2*)&out_override[(size_t)m * DM + col] = make_float2(ox, oy);
                }
            }
        }
    }
}

// ---------------------------------------------------------------------------
// Position kernel v3: cp.async streaming. CTA=(t,h), 128 threads.
// rel chunks (64 s x 64 d fp32) stream into a 4-stage smem ring, depth-2
// prefetch. B-frags built by direct fp32 LDS in fragment layout + in-register
// hi/lo split (no bf16 STS, no ldmatrix). A = Q[8x64] (rows 8..15 zero).
// ---------------------------------------------------------------------------
__global__ __launch_bounds__(128) void pos_tc(const float* __restrict__ rel)
{
    extern __shared__ __align__(16) float Rs[];   // 4 stages x [64][68] fp32
    const uint32_t sRs = smem_u32(Rs);

    const int t = blockIdx.x;
    const int h = blockIdx.y;
    const int tid  = threadIdx.x;
    const int wid  = tid >> 5;
    const int lane = tid & 31;

    // --- A fragments from fp32 Q (log2e-scaled): rows = batch 0..7 ---
    uint32_t qa_h[4][2], qa_l[4][2];
    {
        const int b_ = lane >> 2;
        const int kk = (lane & 3) * 2;
        const float* qrow = &g_Q[(((size_t)b_ * NHH + h) * TT + t) * DHH];
        #pragma unroll
        for (int ks = 0; ks < 4; ks++) {
            float2 f0 = *(const float2*)&qrow[ks * 16 + kk];
            float2 f1 = *(const float2*)&qrow[ks * 16 + kk + 8];
            float h00 = __bfloat162float(__float2bfloat16(f0.x));
            float h01 = __bfloat162float(__float2bfloat16(f0.y));
            float h10 = __bfloat162float(__float2bfloat16(f1.x));
            float h11 = __bfloat162float(__float2bfloat16(f1.y));
            qa_h[ks][0] = pack_bf16(h00, h01);
            qa_h[ks][1] = pack_bf16(h10, h11);
            qa_l[ks][0] = pack_bf16(f0.x - h00, f0.y - h01);
            qa_l[ks][1] = pack_bf16(f1.x - h10, f1.y - h11);
        }
    }

    const float* gbase = rel + (size_t)t * TT * DM + (size_t)h * DHH;

    // cp.async one 64-s chunk into ring stage (c&3):
    // 64 rows x 16 float4; thread covers idx = it*128+tid (16 thr per row).
    #define POSLOAD(c_) do { \
        const float* gsc = gbase + (size_t)(c_) * 64 * DM; \
        const uint32_t sst = sRs + (uint32_t)((c_) & 3) * 17408u; \
        _Pragma("unroll") \
        for (int it = 0; it < 8; it++) { \
            const int idx = it * 128 + tid; \
            const int r_ = idx >> 4, c4 = (idx & 15) * 4; \
            CPASYNC16(sst + (uint32_t)(r_ * 68 + c4) * 4, gsc + (size_t)r_ * DM + c4); \
        } \
        CPASYNC_COMMIT(); \
    } while (0)

    POSLOAD(0);
    POSLOAD(1);

    float* Pout = &g_P[(((size_t)(lane >> 2) * NHH + h) * TT + t) * TT];
    const int scol0 = wid * 16 + (lane & 3) * 2;
    const int srow  = lane >> 2;           // s-row within 8-row n-tile
    const int kcol  = (lane & 3) * 2;      // k offset within fragment

    for (int c = 0; c < 8; c++) {
        if (c < 6)      { POSLOAD(c + 2); CPASYNC_WAIT2(); }
        else if (c == 6){ CPASYNC_WAIT1(); }
        else            { CPASYNC_WAIT0(); }
        __syncthreads();

        const float* S = Rs + (size_t)(c & 3) * (64 * 68);

        float acc[2][4];
        #pragma unroll
        for (int q = 0; q < 2; q++)
            #pragma unroll
            for (int v = 0; v < 4; v++) acc[q][v] = 0.f;

        #pragma unroll
        for (int ks = 0; ks < 4; ks++) {
            uint32_t a_h[4] = {qa_h[ks][0], 0u, qa_h[ks][1], 0u};
            uint32_t a_l[4] = {qa_l[ks][0], 0u, qa_l[ks][1], 0u};
            #pragma unroll
            for (int q = 0; q < 2; q++) {
                const float* row = S + (size_t)(wid * 16 + q * 8 + srow) * 68 + ks * 16 + kcol;
                const float2 x0 = *(const float2*)row;
                const float2 x1 = *(const float2*)(row + 8);
                const float h00 = __bfloat162float(__float2bfloat16(x0.x));
                const float h01 = __bfloat162float(__float2bfloat16(x0.y));
                const float h10 = __bfloat162float(__float2bfloat16(x1.x));
                const float h11 = __bfloat162float(__float2bfloat16(x1.y));
                uint32_t bh[2], bl[2];
                bh[0] = pack_bf16(h00, h01);
                bh[1] = pack_bf16(h10, h11);
                bl[0] = pack_bf16(x0.x - h00, x0.y - h01);
                bl[1] = pack_bf16(x1.x - h10, x1.y - h11);
                mma_bf16(acc[q], a_h, bh);
                mma_bf16(acc[q], a_h, bl);
                mma_bf16(acc[q], a_l, bh);
            }
        }

        #pragma unroll
        for (int q = 0; q < 2; q++) {
            const int s = c * 64 + scol0 + q * 8;
            *(float2*)&Pout[s] = make_float2(acc[q][0], acc[q][1]);
        }
        // no trailing sync: stage (c+2)&3 overwritten at issue-time of c
        // was consumed at c-2; barrier above bounds warp skew to 1 iter.
    }
    #undef POSLOAD
}

// ---------------------------------------------------------------------------
// Tensor-core flash attention with 3-stage cp.async K/V pipeline (unchanged)
// ---------------------------------------------------------------------------
__global__ __launch_bounds__(256) void attn_tc()
{
    extern __shared__ __nv_bfloat16 smb[];
    __nv_bfloat16* Qh = smb;
    __nv_bfloat16* Ql = Qh + 128*72;

    const int tc = blockIdx.x, h = blockIdx.y, b_ = blockIdx.z;
    const int tid  = threadIdx.x;
    const int wid  = tid >> 5;
    const int lane = tid & 31;

    const size_t headoff = ((size_t)b_ * NHH + h) * TT * DHH;
    const __nv_bfloat16* gQh = g_Qh + headoff + (size_t)tc * 128 * DHH;
    const __nv_bfloat16* gQl = g_Ql + headoff + (size_t)tc * 128 * DHH;
    const __nv_bfloat16* gKh = g_Kh + headoff;
    const __nv_bfloat16* gKl = g_Kl + headoff;
    const __nv_bfloat16* gVh = g_Vh + headoff;
    const __nv_bfloat16* gVl = g_Vl + headoff;
    const float* Pg = g_P + (((size_t)b_ * NHH + h) * TT + tc * 128) * TT;

    const uint32_t sbase = smem_u32(smb);

    #pragma unroll
    for (int it = 0; it < 4; it++) {
        const int idx = it * 256 + tid;
        const int r = idx >> 3, c = (idx & 7) * 8;
        *(uint4*)&Qh[r * 72 + c] = *(const uint4*)&gQh[r * 64 + c];
        *(uint4*)&Ql[r * 72 + c] = *(const uint4*)&gQl[r * 64 + c];
    }

    #define PREFETCH(sc_, st_) do { \
        const uint32_t so = sbase + 36864u + (uint32_t)(st_) * 36864u; \
        _Pragma("unroll") \
        for (int it = 0; it < 2; it++) { \
            const int idx = it * 256 + tid; \
            const int r = idx >> 3, c = (idx & 7) * 8; \
            const uint32_t d = (uint32_t)(r * 72 + c) * 2; \
            const size_t g = (size_t)((sc_) * 64 + r) * 64 + c; \
            CPASYNC16(so + d,          gKh + g); \
            CPASYNC16(so +  9216u + d, gKl + g); \
            CPASYNC16(so + 18432u + d, gVh + g); \
            CPASYNC16(so + 27648u + d, gVl + g); \
        } \
        CPASYNC_COMMIT(); \
    } while (0)

    const int wm = wid * 16;
    const int ar = (lane & 7) + ((lane >> 3) & 1) * 8;
    const int ak = ((lane >> 4) & 1) * 8;
    const int br = (lane & 7) + ((lane >> 4) & 1) * 8;
    const int bk = ((lane >> 3) & 1) * 8;
    const int vr = lane & 15;
    const int vc = ((lane >> 4) & 1) * 8;

    const uint32_t sQh = sbase, sQl = sbase + 18432u;

    float acc_d[8][4];
    #pragma unroll
    for (int nt = 0; nt < 8; nt++)
        #pragma unroll
        for (int v = 0; v < 4; v++) acc_d[nt][v] = 0.f;
    float m_run[2] = {-INFINITY, -INFINITY};
    float l_run[2] = {0.f, 0.f};

    PREFETCH(0, 0);

    for (int sc = 0; sc < 8; sc++) {
        const int st = sc % 3;
        if (sc < 7) { PREFETCH(sc + 1, (sc + 1) % 3); CPASYNC_WAIT1(); }
        else        { CPASYNC_WAIT0(); }
        __syncthreads();

        const uint32_t sKh = sbase + 36864u + (uint32_t)st * 36864u;
        const uint32_t sKl = sKh +  9216u;
        const uint32_t sVh = sKh + 18432u;
        const uint32_t sVl = sKh + 27648u;

        float acc_s[8][4];
        #pragma unroll
        for (int nt = 0; nt < 8; nt++) {
            const int scol = sc * 64 + nt * 8 + 2 * (lane & 3);
            #pragma unroll
            for (int half = 0; half < 2; half++) {
                const int trow = wm + (lane >> 2) + half * 8;
                float2 pv = *(const float2*)&Pg[(size_t)trow * TT + scol];
                acc_s[nt][half * 2 + 0] = pv.x;
                acc_s[nt][half * 2 + 1] = pv.y;
            }
        }

        #pragma unroll
        for (int ks = 0; ks < 4; ks++) {
            uint32_t ah[4], al[4];
            const uint32_t ao = (uint32_t)((wm + ar) * 72 + ks * 16 + ak) * 2;
            ldm_x4(ah, sQh + ao);
            ldm_x4(al, sQl + ao);
            #pragma unroll
            for (int p = 0; p < 4; p++) {
                uint32_t bh[4], bl[4];
                const uint32_t bo = (uint32_t)((p * 16 + br) * 72 + ks * 16 + bk) * 2;
                ldm_x4(bh, sKh + bo);
                ldm_x4(bl, sKl + bo);
                #pragma unroll
                for (int q = 0; q < 2; q++) {
                    const int nt = p * 2 + q;
                    mma_bf16(acc_s[nt], ah, &bh[q * 2]);
                    mma_bf16(acc_s[nt], ah, &bl[q * 2]);
                    mma_bf16(acc_s[nt], al, &bh[q * 2]);
                }
            }
        }

        float alpha[2];
        #pragma unroll
        for (int half = 0; half < 2; half++) {
            float mx = m_run[half];
            #pragma unroll
            for (int nt = 0; nt < 8; nt++)
                mx = fmaxf(mx, fmaxf(acc_s[nt][half*2], acc_s[nt][half*2+1]));
            mx = fmaxf(mx, __shfl_xor_sync(0xffffffffu, mx, 1));
            mx = fmaxf(mx, __shfl_xor_sync(0xffffffffu, mx, 2));
            alpha[half] = ex2f(m_run[half] - mx);
            float sum = 0.f;
            #pragma unroll
            for (int nt = 0; nt < 8; nt++) {
                float p0 = ex2f(acc_s[nt][half*2]   - mx);
                float p1 = ex2f(acc_s[nt][half*2+1] - mx);
                acc_s[nt][half*2]   = p0;
                acc_s[nt][half*2+1] = p1;
                sum += p0 + p1;
            }
            sum += __shfl_xor_sync(0xffffffffu, sum, 1);
            sum += __shfl_xor_sync(0xffffffffu, sum, 2);
            m_run[half] = mx;
            l_run[half] = l_run[half] * alpha[half] + sum;
        }
        #pragma unroll
        for (int nt = 0; nt < 8; nt++) {
            acc_d[nt][0] *= alpha[0]; acc_d[nt][1] *= alpha[0];
            acc_d[nt][2] *= alpha[1]; acc_d[nt][3] *= alpha[1];
        }

        #pragma unroll
        for (int ks = 0; ks < 4; ks++) {
            uint32_t pa_h[4], pa_l[4];
            #pragma unroll
            for (int rr = 0; rr < 4; rr++) {
                const int nt = 2 * ks + (rr >> 1);
                const float p0 = acc_s[nt][(rr & 1) * 2 + 0];
                const float p1 = acc_s[nt][(rr & 1) * 2 + 1];
                const float h0 = __bfloat162float(__float2bfloat16(p0));
                const float h1 = __bfloat162float(__float2bfloat16(p1));
                pa_h[rr] = pack_bf16(h0, h1);
                pa_l[rr] = pack_bf16(p0 - h0, p1 - h1);
            }
            #pragma unroll
            for (int dp = 0; dp < 4; dp++) {
                uint32_t vh[4], vl[4];
                const uint32_t vo = (uint32_t)((ks * 16 + vr) * 72 + dp * 16 + vc) * 2;
                ldm_x4_trans(vh, sVh + vo);
                ldm_x4_trans(vl, sVl + vo);
                #pragma unroll
                for (int q = 0; q < 2; q++) {
                    const int nt = dp * 2 + q;
                    mma_bf16(acc_d[nt], pa_h, &vh[q * 2]);
                    mma_bf16(acc_d[nt], pa_h, &vl[q * 2]);
                    mma_bf16(acc_d[nt], pa_l, &vh[q * 2]);
                }
            }
        }
    }
    #undef PREFETCH

    const float inv0 = 1.f / l_run[0];
    const float inv1 = 1.f / l_run[1];
    #pragma unroll
    for (int nt = 0; nt < 8; nt++) {
        const int d = nt * 8 + 2 * (lane & 3);
        #pragma unroll
        for (int half = 0; half < 2; half++) {
            const int t_g = tc * 128 + wm + (lane >> 2) + half * 8;
            const float inv = half ? inv1 : inv0;
            float2 o;
            o.x = acc_d[nt][half * 2 + 0] * inv;
            o.y = acc_d[nt][half * 2 + 1] * inv;
            *(float2*)&g_ctx[((size_t)b_ * TT + t_g) * DM + h * DHH + d] = o;
        }
    }
}

// ---------------------------------------------------------------------------
extern "C" void kernel_launch(void* const* d_in, const int* in_sizes, int n_in,
                              void* d_out, int out_size)
{
    const float* x   = (const float*)d_in[0];
    const float* rel = (const float*)d_in[1];
    const float* Wq  = (const float*)d_in[2];
    const float* bq  = (const float*)d_in[3];
    const float* Wk  = (const float*)d_in[4];
    const float* bk  = (const float*)d_in[5];
    const float* Wv  = (const float*)d_in[6];
    const float* bv  = (const float*)d_in[7];
    const float* Wo  = (const float*)d_in[8];
    const float* bo  = (const float*)d_in[9];

    (void)in_sizes; (void)n_in; (void)out_size;

    cudaFuncSetAttribute(attn_tc, cudaFuncAttributeMaxDynamicSharedMemorySize, 147456);
    cudaFuncSetAttribute(pos_tc,  cudaFuncAttributeMaxDynamicSharedMemorySize, 69632);

    __nv_bfloat16 *pAhi, *pAlo, *pWhi, *pWlo;
    cudaGetSymbolAddress((void**)&pAhi, g_Ahi);
    cudaGetSymbolAddress((void**)&pAlo, g_Alo);
    cudaGetSymbolAddress((void**)&pWhi, g_Whi);
    cudaGetSymbolAddress((void**)&pWlo, g_Wlo);
    float* pctx;
    cudaGetSymbolAddress((void**)&pctx, g_ctx);

    convert_split<<<1024, 256>>>(x, pAhi, pAlo, BB*TT*DM);
    convert_split_w<<<dim3(64, 4), 256>>>(Wq, Wk, Wv, Wo, pWhi, pWlo);

    gemm_tc<0><<<dim3(32, 4, 3), 256>>>(pAhi, pAlo, pWhi, pWlo, bq, bk, bv, nullptr);

    pos_tc<<<dim3(512, 8), 128, 69632>>>(rel);
    attn_tc<<<dim3(4, 8, 8), 256, 147456>>>();

    convert_split<<<1024, 256>>>(pctx, pAhi, pAlo, BB*TT*DM);
    gemm_tc<1><<<dim3(32, 4, 1), 256>>>(pAhi, pAlo, pWhi + 3*DM*DM, pWlo + 3*DM*DM,
                                        bo, nullptr, nullptr, (float*)d_out);
}

// round 9
// speedup vs baseline: 2.3994x; 1.0189x over previous
#include <cuda_runtime.h>
#include <cuda_bf16.h>
#include <math.h>
#include <stdint.h>

#define BB  8
#define TT  512
#define DM  512
#define NHH 8
#define DHH 64
#define LOG2E 1.4426950408889634f

// ---------------------------------------------------------------------------
// Scratch (static __device__ — no allocations allowed)
// ---------------------------------------------------------------------------
__device__ float g_Q[BB*NHH*TT*DHH];        // [B,NH,T,DH] fp32, scaled by log2e/8
__device__ float g_P[BB*NHH*TT*TT];         // position scores (log2 units)
__device__ float g_ctx[BB*TT*DM];           // attention context [B,T,D]
__device__ __nv_bfloat16 g_Ahi[BB*TT*DM];
__device__ __nv_bfloat16 g_Alo[BB*TT*DM];
__device__ __nv_bfloat16 g_Whi[4*DM*DM];
__device__ __nv_bfloat16 g_Wlo[4*DM*DM];
__device__ __nv_bfloat16 g_Qh[BB*NHH*TT*DHH], g_Ql[BB*NHH*TT*DHH];
__device__ __nv_bfloat16 g_Kh[BB*NHH*TT*DHH], g_Kl[BB*NHH*TT*DHH];
__device__ __nv_bfloat16 g_Vh[BB*NHH*TT*DHH], g_Vl[BB*NHH*TT*DHH];

// ---------------------------------------------------------------------------
// helpers
// ---------------------------------------------------------------------------
__device__ __forceinline__ uint32_t smem_u32(const void* p) {
    uint32_t a;
    asm("{ .reg .u64 t; cvta.to.shared.u64 t, %1; cvt.u32.u64 %0, t; }" : "=r"(a) : "l"(p));
    return a;
}
__device__ __forceinline__ void ldm_x4(uint32_t* r, uint32_t addr) {
    asm volatile("ldmatrix.sync.aligned.m8n8.x4.shared.b16 {%0,%1,%2,%3}, [%4];"
        : "=r"(r[0]), "=r"(r[1]), "=r"(r[2]), "=r"(r[3]) : "r"(addr));
}
__device__ __forceinline__ void ldm_x4_trans(uint32_t* r, uint32_t addr) {
    asm volatile("ldmatrix.sync.aligned.m8n8.x4.trans.shared.b16 {%0,%1,%2,%3}, [%4];"
        : "=r"(r[0]), "=r"(r[1]), "=r"(r[2]), "=r"(r[3]) : "r"(addr));
}
__device__ __forceinline__ void mma_bf16(float* d, const uint32_t* a, const uint32_t* b) {
    asm volatile("mma.sync.aligned.m16n8k16.row.col.f32.bf16.bf16.f32 "
        "{%0,%1,%2,%3}, {%4,%5,%6,%7}, {%8,%9}, {%0,%1,%2,%3};"
        : "+f"(d[0]), "+f"(d[1]), "+f"(d[2]), "+f"(d[3])
        : "r"(a[0]), "r"(a[1]), "r"(a[2]), "r"(a[3]), "r"(b[0]), "r"(b[1]));
}
__device__ __forceinline__ uint32_t pack_bf16(float lo, float hi) {
    __nv_bfloat162 t = __floats2bfloat162_rn(lo, hi);
    return *reinterpret_cast<uint32_t*>(&t);
}
__device__ __forceinline__ float ex2f(float x) {
    float r; asm("ex2.approx.ftz.f32 %0, %1;" : "=f"(r) : "f"(x)); return r;
}
#define CPASYNC16(daddr, sptr) \
    asm volatile("cp.async.cg.shared.global [%0], [%1], 16;" :: "r"(daddr), "l"(sptr) : "memory")
#define CPASYNC_COMMIT() asm volatile("cp.async.commit_group;" ::: "memory")
#define CPASYNC_WAIT2()  asm volatile("cp.async.wait_group 2;" ::: "memory")
#define CPASYNC_WAIT1()  asm volatile("cp.async.wait_group 1;" ::: "memory")
#define CPASYNC_WAIT0()  asm volatile("cp.async.wait_group 0;" ::: "memory")

// ---------------------------------------------------------------------------
// fp32 -> bf16 (hi, lo) split conversion
// ---------------------------------------------------------------------------
__device__ __forceinline__ void split_store(const float* src, __nv_bfloat16* hi,
                                            __nv_bfloat16* lo, int i)
{
    float4 v = ((const float4*)src)[i];
    float f[4] = {v.x, v.y, v.z, v.w};
    unsigned short hb[4], lb[4];
    #pragma unroll
    for (int j = 0; j < 4; j++) {
        __nv_bfloat16 h = __float2bfloat16(f[j]);
        __nv_bfloat16 l = __float2bfloat16(f[j] - __bfloat162float(h));
        hb[j] = *reinterpret_cast<unsigned short*>(&h);
        lb[j] = *reinterpret_cast<unsigned short*>(&l);
    }
    ((ushort4*)hi)[i] = make_ushort4(hb[0], hb[1], hb[2], hb[3]);
    ((ushort4*)lo)[i] = make_ushort4(lb[0], lb[1], lb[2], lb[3]);
}

__global__ __launch_bounds__(256) void convert_split(
    const float* __restrict__ src, __nv_bfloat16* __restrict__ hi,
    __nv_bfloat16* __restrict__ lo, int n)
{
    const int n4 = n >> 2;
    for (int i = blockIdx.x * blockDim.x + threadIdx.x; i < n4; i += gridDim.x * blockDim.x)
        split_store(src, hi, lo, i);
}

__global__ __launch_bounds__(256) void convert_split_w(
    const float* __restrict__ w0, const float* __restrict__ w1,
    const float* __restrict__ w2, const float* __restrict__ w3,
    __nv_bfloat16* __restrict__ hi, __nv_bfloat16* __restrict__ lo)
{
    const int z = blockIdx.y;
    const float* src = (z == 0) ? w0 : (z == 1) ? w1 : (z == 2) ? w2 : w3;
    __nv_bfloat16* h = hi + (size_t)z * DM * DM;
    __nv_bfloat16* l = lo + (size_t)z * DM * DM;
    const int n4 = (DM * DM) >> 2;
    for (int i = blockIdx.x * blockDim.x + threadIdx.x; i < n4; i += gridDim.x * blockDim.x)
        split_store(src, h, l, i);
}

// ---------------------------------------------------------------------------
// mma.sync split-bf16 GEMM (unchanged)
// ---------------------------------------------------------------------------
template<int MODE>
__global__ __launch_bounds__(256) void gemm_tc(
    const __nv_bfloat16* __restrict__ Ahi, const __nv_bfloat16* __restrict__ Alo,
    const __nv_bfloat16* __restrict__ Whi, const __nv_bfloat16* __restrict__ Wlo,
    const float* __restrict__ bias0, const float* __restrict__ bias1,
    const float* __restrict__ bias2, float* __restrict__ out_override)
{
    __shared__ __align__(16) __nv_bfloat16 As[2][128][40];
    __shared__ __align__(16) __nv_bfloat16 Bs[2][128][40];

    const int tid  = threadIdx.x;
    const int wid  = tid >> 5;
    const int lane = tid & 31;
    const int m0 = blockIdx.x * 128;
    const int n0 = blockIdx.y * 128;
    const int z  = blockIdx.z;

    const float* bias; float scale;
    const __nv_bfloat16 *Wh, *Wl;
    __nv_bfloat16 *oh, *ol;
    if (MODE == 0) {
        bias  = (z == 0) ? bias0 : (z == 1) ? bias1 : bias2;
        scale = (z == 0) ? 0.125f * LOG2E : 1.0f;
        oh = (z == 0) ? g_Qh : (z == 1) ? g_Kh : g_Vh;
        ol = (z == 0) ? g_Ql : (z == 1) ? g_Kl : g_Vl;
        Wh = Whi + (size_t)z * DM * DM;
        Wl = Wlo + (size_t)z * DM * DM;
    } else {
        bias = bias0; scale = 1.0f;
        Wh = Whi; Wl = Wlo; oh = nullptr; ol = nullptr;
    }

    const int grow = tid >> 1;
    const int gcol = (tid & 1) * 16;
    const __nv_bfloat16* gA = Ahi + (size_t)(m0 + grow) * DM + gcol;
    const __nv_bfloat16* gAl= Alo + (size_t)(m0 + grow) * DM + gcol;
    const __nv_bfloat16* gB = Wh  + (size_t)(n0 + grow) * DM + gcol;
    const __nv_bfloat16* gBl= Wl  + (size_t)(n0 + grow) * DM + gcol;

    uint4 pAh[2], pAl[2], pBh[2], pBl[2];
    #define LOAD_REGS(kc) do { \
        const int off = (kc) * 32; \
        pAh[0] = *(const uint4*)(gA  + off); pAh[1] = *(const uint4*)(gA  + off + 8); \
        pAl[0] = *(const uint4*)(gAl + off); pAl[1] = *(const uint4*)(gAl + off + 8); \
        pBh[0] = *(const uint4*)(gB  + off); pBh[1] = *(const uint4*)(gB  + off + 8); \
        pBl[0] = *(const uint4*)(gBl + off); pBl[1] = *(const uint4*)(gBl + off + 8); \
    } while (0)

    float acc[4][4][4];
    #pragma unroll
    for (int i = 0; i < 4; i++)
        #pragma unroll
        for (int j = 0; j < 4; j++)
            #pragma unroll
            for (int v = 0; v < 4; v++) acc[i][j][v] = 0.f;

    const int wm = (wid >> 2) * 64;
    const int wn = (wid & 3) * 32;
    const int ar = (lane & 7) + ((lane >> 3) & 1) * 8;
    const int ak = ((lane >> 4) & 1) * 8;
    const int br = (lane & 7) + ((lane >> 4) & 1) * 8;
    const int bk = ((lane >> 3) & 1) * 8;

    const uint32_t aBase = smem_u32(&As[0][0][0]);
    const uint32_t bBase = smem_u32(&Bs[0][0][0]);
    const uint32_t bufStride = 128 * 40 * 2;

    LOAD_REGS(0);

    for (int kc = 0; kc < 16; kc++) {
        __syncthreads();
        *(uint4*)&As[0][grow][gcol]     = pAh[0];
        *(uint4*)&As[0][grow][gcol + 8] = pAh[1];
        *(uint4*)&As[1][grow][gcol]     = pAl[0];
        *(uint4*)&As[1][grow][gcol + 8] = pAl[1];
        *(uint4*)&Bs[0][grow][gcol]     = pBh[0];
        *(uint4*)&Bs[0][grow][gcol + 8] = pBh[1];
        *(uint4*)&Bs[1][grow][gcol]     = pBl[0];
        *(uint4*)&Bs[1][grow][gcol + 8] = pBl[1];
        __syncthreads();

        if (kc < 15) LOAD_REGS(kc + 1);

        #pragma unroll
        for (int ks = 0; ks < 2; ks++) {
            uint32_t ah[4][4], al[4][4];
            #pragma unroll
            for (int mt = 0; mt < 4; mt++) {
                const uint32_t ao = (uint32_t)((wm + mt * 16 + ar) * 40 + ks * 16 + ak) * 2;
                ldm_x4(ah[mt], aBase + ao);
                ldm_x4(al[mt], aBase + bufStride + ao);
            }
            uint32_t bh[2][4], bl[2][4];
            #pragma unroll
            for (int p = 0; p < 2; p++) {
                const uint32_t bo = (uint32_t)((wn + p * 16 + br) * 40 + ks * 16 + bk) * 2;
                ldm_x4(bh[p], bBase + bo);
                ldm_x4(bl[p], bBase + bufStride + bo);
            }
            #pragma unroll
            for (int mt = 0; mt < 4; mt++)
                #pragma unroll
                for (int nt = 0; nt < 4; nt++) {
                    const int p = nt >> 1, o = (nt & 1) * 2;
                    mma_bf16(acc[mt][nt], ah[mt], &bh[p][o]);
                    mma_bf16(acc[mt][nt], ah[mt], &bl[p][o]);
                    mma_bf16(acc[mt][nt], al[mt], &bh[p][o]);
                }
        }
    }
    #undef LOAD_REGS

    #pragma unroll
    for (int mt = 0; mt < 4; mt++) {
        #pragma unroll
        for (int nt = 0; nt < 4; nt++) {
            const int col = n0 + wn + nt * 8 + 2 * (lane & 3);
            const float bx = bias[col], by = bias[col + 1];
            #pragma unroll
            for (int half = 0; half < 2; half++) {
                const int m = m0 + wm + mt * 16 + (lane >> 2) + half * 8;
                float ox = (acc[mt][nt][half * 2 + 0] + bx) * scale;
                float oy = (acc[mt][nt][half * 2 + 1] + by) * scale;
                if (MODE == 0) {
                    const int b_ = m >> 9, t = m & 511, h = col >> 6, d = col & 63;
                    const size_t idx = (((size_t)b_ * NHH + h) * TT + t) * DHH + d;
                    __nv_bfloat16 hx = __float2bfloat16(ox);
                    __nv_bfloat16 hy = __float2bfloat16(oy);
                    __nv_bfloat16 lx = __float2bfloat16(ox - __bfloat162float(hx));
                    __nv_bfloat16 ly = __float2bfloat16(oy - __bfloat162float(hy));
                    *(__nv_bfloat162*)&oh[idx] = __nv_bfloat162(hx, hy);
                    *(__nv_bfloat162*)&ol[idx] = __nv_bfloat162(lx, ly);
                    if (z == 0) *(float2*)&g_Q[idx] = make_float2(ox, oy);
                } else {
                    *(float2*)&out_override[(size_t)m * DM + col] = make_float2(ox, oy);
                }
            }
        }
    }
}

// ---------------------------------------------------------------------------
// Position kernel v3: cp.async streaming (unchanged — 80% DRAM)
// ---------------------------------------------------------------------------
__global__ __launch_bounds__(128) void pos_tc(const float* __restrict__ rel)
{
    extern __shared__ __align__(16) float Rs[];   // 4 stages x [64][68] fp32
    const uint32_t sRs = smem_u32(Rs);

    const int t = blockIdx.x;
    const int h = blockIdx.y;
    const int tid  = threadIdx.x;
    const int wid  = tid >> 5;
    const int lane = tid & 31;

    uint32_t qa_h[4][2], qa_l[4][2];
    {
        const int b_ = lane >> 2;
        const int kk = (lane & 3) * 2;
        const float* qrow = &g_Q[(((size_t)b_ * NHH + h) * TT + t) * DHH];
        #pragma unroll
        for (int ks = 0; ks < 4; ks++) {
            float2 f0 = *(const float2*)&qrow[ks * 16 + kk];
            float2 f1 = *(const float2*)&qrow[ks * 16 + kk + 8];
            float h00 = __bfloat162float(__float2bfloat16(f0.x));
            float h01 = __bfloat162float(__float2bfloat16(f0.y));
            float h10 = __bfloat162float(__float2bfloat16(f1.x));
            float h11 = __bfloat162float(__float2bfloat16(f1.y));
            qa_h[ks][0] = pack_bf16(h00, h01);
            qa_h[ks][1] = pack_bf16(h10, h11);
            qa_l[ks][0] = pack_bf16(f0.x - h00, f0.y - h01);
            qa_l[ks][1] = pack_bf16(f1.x - h10, f1.y - h11);
        }
    }

    const float* gbase = rel + (size_t)t * TT * DM + (size_t)h * DHH;

    #define POSLOAD(c_) do { \
        const float* gsc = gbase + (size_t)(c_) * 64 * DM; \
        const uint32_t sst = sRs + (uint32_t)((c_) & 3) * 17408u; \
        _Pragma("unroll") \
        for (int it = 0; it < 8; it++) { \
            const int idx = it * 128 + tid; \
            const int r_ = idx >> 4, c4 = (idx & 15) * 4; \
            CPASYNC16(sst + (uint32_t)(r_ * 68 + c4) * 4, gsc + (size_t)r_ * DM + c4); \
        } \
        CPASYNC_COMMIT(); \
    } while (0)

    POSLOAD(0);
    POSLOAD(1);

    float* Pout = &g_P[(((size_t)(lane >> 2) * NHH + h) * TT + t) * TT];
    const int scol0 = wid * 16 + (lane & 3) * 2;
    const int srow  = lane >> 2;
    const int kcol  = (lane & 3) * 2;

    for (int c = 0; c < 8; c++) {
        if (c < 6)      { POSLOAD(c + 2); CPASYNC_WAIT2(); }
        else if (c == 6){ CPASYNC_WAIT1(); }
        else            { CPASYNC_WAIT0(); }
        __syncthreads();

        const float* S = Rs + (size_t)(c & 3) * (64 * 68);

        float acc[2][4];
        #pragma unroll
        for (int q = 0; q < 2; q++)
            #pragma unroll
            for (int v = 0; v < 4; v++) acc[q][v] = 0.f;

        #pragma unroll
        for (int ks = 0; ks < 4; ks++) {
            uint32_t a_h[4] = {qa_h[ks][0], 0u, qa_h[ks][1], 0u};
            uint32_t a_l[4] = {qa_l[ks][0], 0u, qa_l[ks][1], 0u};
            #pragma unroll
            for (int q = 0; q < 2; q++) {
                const float* row = S + (size_t)(wid * 16 + q * 8 + srow) * 68 + ks * 16 + kcol;
                const float2 x0 = *(const float2*)row;
                const float2 x1 = *(const float2*)(row + 8);
                const float h00 = __bfloat162float(__float2bfloat16(x0.x));
                const float h01 = __bfloat162float(__float2bfloat16(x0.y));
                const float h10 = __bfloat162float(__float2bfloat16(x1.x));
                const float h11 = __bfloat162float(__float2bfloat16(x1.y));
                uint32_t bh[2], bl[2];
                bh[0] = pack_bf16(h00, h01);
                bh[1] = pack_bf16(h10, h11);
                bl[0] = pack_bf16(x0.x - h00, x0.y - h01);
                bl[1] = pack_bf16(x1.x - h10, x1.y - h11);
                mma_bf16(acc[q], a_h, bh);
                mma_bf16(acc[q], a_h, bl);
                mma_bf16(acc[q], a_l, bh);
            }
        }

        #pragma unroll
        for (int q = 0; q < 2; q++) {
            const int s = c * 64 + scol0 + q * 8;
            *(float2*)&Pout[s] = make_float2(acc[q][0], acc[q][1]);
        }
    }
    #undef POSLOAD
}

// ---------------------------------------------------------------------------
// Tensor-core flash attention, 2-stage cp.async K/V ring, 2 CTAs/SM.
// Pipeline per iter: WAIT0 -> barrier -> PREFETCH(next) -> compute.
// Race-free at depth 2: prefetch into stage (sc+1)&1 (consumed at sc-1) is
// issued only after the barrier proving all warps finished iter sc-1.
// ---------------------------------------------------------------------------
__global__ __launch_bounds__(256, 2) void attn_tc()
{
    extern __shared__ __nv_bfloat16 smb[];
    __nv_bfloat16* Qh = smb;
    __nv_bfloat16* Ql = Qh + 128*72;

    const int tc = blockIdx.x, h = blockIdx.y, b_ = blockIdx.z;
    const int tid  = threadIdx.x;
    const int wid  = tid >> 5;
    const int lane = tid & 31;

    const size_t headoff = ((size_t)b_ * NHH + h) * TT * DHH;
    const __nv_bfloat16* gQh = g_Qh + headoff + (size_t)tc * 128 * DHH;
    const __nv_bfloat16* gQl = g_Ql + headoff + (size_t)tc * 128 * DHH;
    const __nv_bfloat16* gKh = g_Kh + headoff;
    const __nv_bfloat16* gKl = g_Kl + headoff;
    const __nv_bfloat16* gVh = g_Vh + headoff;
    const __nv_bfloat16* gVl = g_Vl + headoff;
    const float* Pg = g_P + (((size_t)b_ * NHH + h) * TT + tc * 128) * TT;

    const uint32_t sbase = smem_u32(smb);

    #pragma unroll
    for (int it = 0; it < 4; it++) {
        const int idx = it * 256 + tid;
        const int r = idx >> 3, c = (idx & 7) * 8;
        *(uint4*)&Qh[r * 72 + c] = *(const uint4*)&gQh[r * 64 + c];
        *(uint4*)&Ql[r * 72 + c] = *(const uint4*)&gQl[r * 64 + c];
    }

    #define PREFETCH(sc_, st_) do { \
        const uint32_t so = sbase + 36864u + (uint32_t)(st_) * 36864u; \
        _Pragma("unroll") \
        for (int it = 0; it < 2; it++) { \
            const int idx = it * 256 + tid; \
            const int r = idx >> 3, c = (idx & 7) * 8; \
            const uint32_t d = (uint32_t)(r * 72 + c) * 2; \
            const size_t g = (size_t)((sc_) * 64 + r) * 64 + c; \
            CPASYNC16(so + d,          gKh + g); \
            CPASYNC16(so +  9216u + d, gKl + g); \
            CPASYNC16(so + 18432u + d, gVh + g); \
            CPASYNC16(so + 27648u + d, gVl + g); \
        } \
        CPASYNC_COMMIT(); \
    } while (0)

    const int wm = wid * 16;
    const int ar = (lane & 7) + ((lane >> 3) & 1) * 8;
    const int ak = ((lane >> 4) & 1) * 8;
    const int br = (lane & 7) + ((lane >> 4) & 1) * 8;
    const int bk = ((lane >> 3) & 1) * 8;
    const int vr = lane & 15;
    const int vc = ((lane >> 4) & 1) * 8;

    const uint32_t sQh = sbase, sQl = sbase + 18432u;

    float acc_d[8][4];
    #pragma unroll
    for (int nt = 0; nt < 8; nt++)
        #pragma unroll
        for (int v = 0; v < 4; v++) acc_d[nt][v] = 0.f;
    float m_run[2] = {-INFINITY, -INFINITY};
    float l_run[2] = {0.f, 0.f};

    PREFETCH(0, 0);

    for (int sc = 0; sc < 8; sc++) {
        const int st = sc & 1;
        CPASYNC_WAIT0();
        __syncthreads();
        if (sc < 7) PREFETCH(sc + 1, (sc + 1) & 1);

        const uint32_t sKh = sbase + 36864u + (uint32_t)st * 36864u;
        const uint32_t sKl = sKh +  9216u;
        const uint32_t sVh = sKh + 18432u;
        const uint32_t sVl = sKh + 27648u;

        float acc_s[8][4];
        #pragma unroll
        for (int nt = 0; nt < 8; nt++) {
            const int scol = sc * 64 + nt * 8 + 2 * (lane & 3);
            #pragma unroll
            for (int half = 0; half < 2; half++) {
                const int trow = wm + (lane >> 2) + half * 8;
                float2 pv = *(const float2*)&Pg[(size_t)trow * TT + scol];
                acc_s[nt][half * 2 + 0] = pv.x;
                acc_s[nt][half * 2 + 1] = pv.y;
            }
        }

        #pragma unroll
        for (int ks = 0; ks < 4; ks++) {
            uint32_t ah[4], al[4];
            const uint32_t ao = (uint32_t)((wm + ar) * 72 + ks * 16 + ak) * 2;
            ldm_x4(ah, sQh + ao);
            ldm_x4(al, sQl + ao);
            #pragma unroll
            for (int p = 0; p < 4; p++) {
                uint32_t bh[4], bl[4];
                const uint32_t bo = (uint32_t)((p * 16 + br) * 72 + ks * 16 + bk) * 2;
                ldm_x4(bh, sKh + bo);
                ldm_x4(bl, sKl + bo);
                #pragma unroll
                for (int q = 0; q < 2; q++) {
                    const int nt = p * 2 + q;
                    mma_bf16(acc_s[nt], ah, &bh[q * 2]);
                    mma_bf16(acc_s[nt], ah, &bl[q * 2]);
                    mma_bf16(acc_s[nt], al, &bh[q * 2]);
                }
            }
        }

        float alpha[2];
        #pragma unroll
        for (int half = 0; half < 2; half++) {
            float mx = m_run[half];
            #pragma unroll
            for (int nt = 0; nt < 8; nt++)
                mx = fmaxf(mx, fmaxf(acc_s[nt][half*2], acc_s[nt][half*2+1]));
            mx = fmaxf(mx, __shfl_xor_sync(0xffffffffu, mx, 1));
            mx = fmaxf(mx, __shfl_xor_sync(0xffffffffu, mx, 2));
            alpha[half] = ex2f(m_run[half] - mx);
            float sum = 0.f;
            #pragma unroll
            for (int nt = 0; nt < 8; nt++) {
                float p0 = ex2f(acc_s[nt][half*2]   - mx);
                float p1 = ex2f(acc_s[nt][half*2+1] - mx);
                acc_s[nt][half*2]   = p0;
                acc_s[nt][half*2+1] = p1;
                sum += p0 + p1;
            }
            sum += __shfl_xor_sync(0xffffffffu, sum, 1);
            sum += __shfl_xor_sync(0xffffffffu, sum, 2);
            m_run[half] = mx;
            l_run[half] = l_run[half] * alpha[half] + sum;
        }
        #pragma unroll
        for (int nt = 0; nt < 8; nt++) {
            acc_d[nt][0] *= alpha[0]; acc_d[nt][1] *= alpha[0];
            acc_d[nt][2] *= alpha[1]; acc_d[nt][3] *= alpha[1];
        }

        #pragma unroll
        for (int ks = 0; ks < 4; ks++) {
            uint32_t pa_h[4], pa_l[4];
            #pragma unroll
            for (int rr = 0; rr < 4; rr++) {
                const int nt = 2 * ks + (rr >> 1);
                const float p0 = acc_s[nt][(rr & 1) * 2 + 0];
                const float p1 = acc_s[nt][(rr & 1) * 2 + 1];
                const float h0 = __bfloat162float(__float2bfloat16(p0));
                const float h1 = __bfloat162float(__float2bfloat16(p1));
                pa_h[rr] = pack_bf16(h0, h1);
                pa_l[rr] = pack_bf16(p0 - h0, p1 - h1);
            }
            #pragma unroll
            for (int dp = 0; dp < 4; dp++) {
                uint32_t vh[4], vl[4];
                const uint32_t vo = (uint32_t)((ks * 16 + vr) * 72 + dp * 16 + vc) * 2;
                ldm_x4_trans(vh, sVh + vo);
                ldm_x4_trans(vl, sVl + vo);
                #pragma unroll
                for (int q = 0; q < 2; q++) {
                    const int nt = dp * 2 + q;
                    mma_bf16(acc_d[nt], pa_h, &vh[q * 2]);
                    mma_bf16(acc_d[nt], pa_h, &vl[q * 2]);
                    mma_bf16(acc_d[nt], pa_l, &vh[q * 2]);
                }
            }
        }
    }
    #undef PREFETCH

    const float inv0 = 1.f / l_run[0];
    const float inv1 = 1.f / l_run[1];
    #pragma unroll
    for (int nt = 0; nt < 8; nt++) {
        const int d = nt * 8 + 2 * (lane & 3);
        #pragma unroll
        for (int half = 0; half < 2; half++) {
            const int t_g = tc * 128 + wm + (lane >> 2) + half * 8;
            const float inv = half ? inv1 : inv0;
            float2 o;
            o.x = acc_d[nt][half * 2 + 0] * inv;
            o.y = acc_d[nt][half * 2 + 1] * inv;
            *(float2*)&g_ctx[((size_t)b_ * TT + t_g) * DM + h * DHH + d] = o;
        }
    }
}

// ---------------------------------------------------------------------------
extern "C" void kernel_launch(void* const* d_in, const int* in_sizes, int n_in,
                              void* d_out, int out_size)
{
    const float* x   = (const float*)d_in[0];
    const float* rel = (const float*)d_in[1];
    const float* Wq  = (const float*)d_in[2];
    const float* bq  = (const float*)d_in[3];
    const float* Wk  = (const float*)d_in[4];
    const float* bk  = (const float*)d_in[5];
    const float* Wv  = (const float*)d_in[6];
    const float* bv  = (const float*)d_in[7];
    const float* Wo  = (const float*)d_in[8];
    const float* bo  = (const float*)d_in[9];

    (void)in_sizes; (void)n_in; (void)out_size;

    cudaFuncSetAttribute(attn_tc, cudaFuncAttributeMaxDynamicSharedMemorySize, 110592);
    cudaFuncSetAttribute(pos_tc,  cudaFuncAttributeMaxDynamicSharedMemorySize, 69632);

    __nv_bfloat16 *pAhi, *pAlo, *pWhi, *pWlo;
    cudaGetSymbolAddress((void**)&pAhi, g_Ahi);
    cudaGetSymbolAddress((void**)&pAlo, g_Alo);
    cudaGetSymbolAddress((void**)&pWhi, g_Whi);
    cudaGetSymbolAddress((void**)&pWlo, g_Wlo);
    float* pctx;
    cudaGetSymbolAddress((void**)&pctx, g_ctx);

    convert_split<<<1024, 256>>>(x, pAhi, pAlo, BB*TT*DM);
    convert_split_w<<<dim3(64, 4), 256>>>(Wq, Wk, Wv, Wo, pWhi, pWlo);

    gemm_tc<0><<<dim3(32, 4, 3), 256>>>(pAhi, pAlo, pWhi, pWlo, bq, bk, bv, nullptr);

    pos_tc<<<dim3(512, 8), 128, 69632>>>(rel);
    attn_tc<<<dim3(4, 8, 8), 256, 110592>>>();

    convert_split<<<1024, 256>>>(pctx, pAhi, pAlo, BB*TT*DM);
    gemm_tc<1><<<dim3(32, 4, 1), 256>>>(pAhi, pAlo, pWhi + 3*DM*DM, pWlo + 3*DM*DM,
                                        bo, nullptr, nullptr, (float*)d_out);
}